// round 11
// baseline (speedup 1.0000x reference)
#include <cuda_runtime.h>
#include <cuda_bf16.h>
#include <cstdint>

#define HH 128
#define NMAX 50000
#define EMAX 800000
#define BN_EPS 1e-5f
#define APITCH 136
#define WIMG_ELEMS (128 * APITCH)

// ---------------- scratch (no allocations allowed) ----------------
__device__ float g_z[NMAX * HH];
__device__ float g_hA[NMAX * HH];
__device__ float g_hB[NMAX * HH];
__device__ float g_stats[2 * HH];
__device__ int   g_deg[NMAX];
__device__ int   g_slot[EMAX];
__device__ int   g_rowstart[NMAX + 1];
__device__ int   g_csr[EMAX];
__device__ uint2 g_ahi[NMAX * 32];
__device__ uint2 g_alo[NMAX * 32];
__device__ unsigned short g_w[12][WIMG_ELEMS];

// ---------------- prep: all 6 W conversions + zero deg/stats ----------
__global__ void prep_kernel(const float* __restrict__ w0, const float* __restrict__ w1,
                            const float* __restrict__ w2, const float* __restrict__ w3,
                            const float* __restrict__ w4, const float* __restrict__ w5,
                            int N) {
    int b = blockIdx.x;
    int tid = threadIdx.x;
    if (b < 384) {
        int wi = b >> 6;
        int i = ((b & 63) << 8) + tid;
        const float* W;
        switch (wi) {
            case 0: W = w0; break;
            case 1: W = w1; break;
            case 2: W = w2; break;
            case 3: W = w3; break;
            case 4: W = w4; break;
            default: W = w5; break;
        }
        int k = i >> 7, n = i & 127;
        float v = __ldg(&W[i]);
        __nv_bfloat16 h = __float2bfloat16_rn(v);
        __nv_bfloat16 l = __float2bfloat16_rn(v - __bfloat162float(h));
        g_w[2 * wi + 0][n * APITCH + k] = __bfloat16_as_ushort(h);
        g_w[2 * wi + 1][n * APITCH + k] = __bfloat16_as_ushort(l);
    } else {
        int idx = (b - 384) * 256 + tid;
        if (idx < N) g_deg[idx] = 0;
        if (b == 384 && tid < 256) g_stats[tid] = 0.f;
    }
}

// ---------------- CSR build ----------------
__global__ void count_kernel(const int* __restrict__ dst, int* __restrict__ deg,
                             int* __restrict__ slot, int E) {
    int e = blockIdx.x * blockDim.x + threadIdx.x;
    if (e < E) slot[e] = atomicAdd(&deg[dst[e]], 1);
}

__global__ void scan_kernel(const int* __restrict__ deg, int* __restrict__ rowstart, int n) {
    __shared__ int warpsum[32];
    __shared__ int s_total;
    __shared__ int s_carry;
    int tid = threadIdx.x, lane = tid & 31, wid = tid >> 5;
    if (tid == 0) s_carry = 0;
    __syncthreads();
    for (int base = 0; base < n; base += 1024) {
        int i = base + tid;
        int v = (i < n) ? deg[i] : 0;
        int incl = v;
#pragma unroll
        for (int off = 1; off < 32; off <<= 1) {
            int t = __shfl_up_sync(0xffffffff, incl, off);
            if (lane >= off) incl += t;
        }
        if (lane == 31) warpsum[wid] = incl;
        __syncthreads();
        if (wid == 0) {
            int w = warpsum[lane];
            int wincl = w;
#pragma unroll
            for (int off = 1; off < 32; off <<= 1) {
                int t = __shfl_up_sync(0xffffffff, wincl, off);
                if (lane >= off) wincl += t;
            }
            warpsum[lane] = wincl - w;
            if (lane == 31) s_total = wincl;
        }
        __syncthreads();
        int carry = s_carry;
        if (i < n) rowstart[i] = carry + warpsum[wid] + incl - v;
        __syncthreads();
        if (tid == 0) s_carry = carry + s_total;
    }
    __syncthreads();
    if (tid == 0) rowstart[n] = s_carry;
}

__global__ void fill_kernel(const int* __restrict__ src, const int* __restrict__ dst,
                            const int* __restrict__ rowstart, const int* __restrict__ slot,
                            int* __restrict__ csr, int E) {
    int e = blockIdx.x * blockDim.x + threadIdx.x;
    if (e >= E) return;
    int d = dst[e];
    csr[__ldg(&rowstart[d]) + slot[e]] = src[e];
}

// ---------------- aggregate -> bf16 hi/lo planes; block 0 zeroes stats -------
__global__ void aggregate_kernel(const float4* __restrict__ h,
                                 const int* __restrict__ rowstart,
                                 const int* __restrict__ csr,
                                 uint2* __restrict__ ahi,
                                 uint2* __restrict__ alo, int N) {
    if (blockIdx.x == 0 && threadIdx.x < 256) g_stats[threadIdx.x] = 0.f;
    int warp = (blockIdx.x * blockDim.x + threadIdx.x) >> 5;
    int lane = threadIdx.x & 31;
    if (warp >= N) return;
    int s0 = rowstart[warp], s1 = rowstart[warp + 1];
    float4 acc = __ldg(&h[(size_t)warp * 32 + lane]);
    int j = s0;
    for (; j + 2 <= s1; j += 2) {
        int sa = __ldg(&csr[j]);
        int sb = __ldg(&csr[j + 1]);
        float4 va = __ldg(&h[(size_t)sa * 32 + lane]);
        float4 vb = __ldg(&h[(size_t)sb * 32 + lane]);
        acc.x += va.x + vb.x; acc.y += va.y + vb.y;
        acc.z += va.z + vb.z; acc.w += va.w + vb.w;
    }
    if (j < s1) {
        int sa = __ldg(&csr[j]);
        float4 va = __ldg(&h[(size_t)sa * 32 + lane]);
        acc.x += va.x; acc.y += va.y; acc.z += va.z; acc.w += va.w;
    }
    float v[4] = {acc.x, acc.y, acc.z, acc.w};
    uint32_t hi[2], lo[2];
#pragma unroll
    for (int p = 0; p < 2; p++) {
        __nv_bfloat16 h0 = __float2bfloat16_rn(v[2 * p]);
        __nv_bfloat16 h1 = __float2bfloat16_rn(v[2 * p + 1]);
        __nv_bfloat16 l0 = __float2bfloat16_rn(v[2 * p] - __bfloat162float(h0));
        __nv_bfloat16 l1 = __float2bfloat16_rn(v[2 * p + 1] - __bfloat162float(h1));
        hi[p] = (uint32_t)__bfloat16_as_ushort(h0) | ((uint32_t)__bfloat16_as_ushort(h1) << 16);
        lo[p] = (uint32_t)__bfloat16_as_ushort(l0) | ((uint32_t)__bfloat16_as_ushort(l1) << 16);
    }
    ahi[(size_t)warp * 32 + lane] = make_uint2(hi[0], hi[1]);
    alo[(size_t)warp * 32 + lane] = make_uint2(lo[0], lo[1]);
}

// ---------------- HMMA GEMM: BM=128, 512 threads (4x4 warps), persistent -----
#define PLANE_BYTES (128 * APITCH * 2)   // 34816
#define SM_SCALE 0
#define SM_SHIFT 512
#define SM_BIAS  1024
#define SM_AHI   1536
#define SM_ALO   (SM_AHI + PLANE_BYTES)
#define SM_BHI   (SM_ALO + PLANE_BYTES)
#define SM_BLO   (SM_BHI + PLANE_BYTES)
#define SM_TOTAL (SM_BLO + PLANE_BYTES)  // 140800

__device__ __forceinline__ void mma16816(float* d, const uint32_t* a, const uint32_t* b) {
    asm volatile(
        "mma.sync.aligned.m16n8k16.row.col.f32.bf16.bf16.f32 "
        "{%0,%1,%2,%3}, {%4,%5,%6,%7}, {%8,%9}, {%0,%1,%2,%3};"
        : "+f"(d[0]), "+f"(d[1]), "+f"(d[2]), "+f"(d[3])
        : "r"(a[0]), "r"(a[1]), "r"(a[2]), "r"(a[3]), "r"(b[0]), "r"(b[1]));
}

__device__ __forceinline__ void split_bf16x2(float a0, float a1,
                                             uint32_t& hi, uint32_t& lo) {
    __nv_bfloat16 h0 = __float2bfloat16_rn(a0);
    __nv_bfloat16 h1 = __float2bfloat16_rn(a1);
    __nv_bfloat16 l0 = __float2bfloat16_rn(a0 - __bfloat162float(h0));
    __nv_bfloat16 l1 = __float2bfloat16_rn(a1 - __bfloat162float(h1));
    hi = (uint32_t)__bfloat16_as_ushort(h0) | ((uint32_t)__bfloat16_as_ushort(h1) << 16);
    lo = (uint32_t)__bfloat16_as_ushort(l0) | ((uint32_t)__bfloat16_as_ushort(l1) << 16);
}

// MODE 0: A from preconverted planes; out=z; fused BN stats
// MODE 1: A = relu(z*scale+shift); out = relu(.)
template <int MODE>
__global__ __launch_bounds__(512, 1) void gemm_mma(
    const float* __restrict__ Af32,
    const uint4* __restrict__ Ahi, const uint4* __restrict__ Alo,
    const uint4* __restrict__ Whi, const uint4* __restrict__ Wlo,
    const float* __restrict__ bias, const float* __restrict__ gamma,
    const float* __restrict__ beta, float inv_n,
    float* __restrict__ out, int nrows, int ntiles) {
    extern __shared__ char smem[];
    int tid = threadIdx.x;
    int lane = tid & 31;
    int wid = tid >> 5;         // 0..15
    int groupID = lane >> 2;
    int tig = lane & 3;
    int warp_m = wid & 3;       // 0..3 -> 32 rows each
    int warp_n = wid >> 2;      // 0..3 -> 32 cols each

    float* sh_scale = (float*)(smem + SM_SCALE);
    float* sh_shift = (float*)(smem + SM_SHIFT);
    float* sh_bias  = (float*)(smem + SM_BIAS);

    // ---- once per CTA: bias/scale + W planes ----
    if (tid < 128) {
        sh_bias[tid] = bias[tid];
        if (MODE == 1) {
            float mu = g_stats[tid] * inv_n;
            float var = fmaf(-mu, mu, g_stats[128 + tid] * inv_n);
            float rs = rsqrtf(var + BN_EPS);
            float sc = gamma[tid] * rs;
            sh_scale[tid] = sc;
            sh_shift[tid] = fmaf(-mu, sc, beta[tid]);
        }
    }
    {
        uint4* dh = (uint4*)(smem + SM_BHI);
        uint4* dl = (uint4*)(smem + SM_BLO);
        for (int i = tid; i < PLANE_BYTES / 16; i += 512) {
            dh[i] = __ldg(&Whi[i]);
            dl[i] = __ldg(&Wlo[i]);
        }
    }
    if (MODE == 1) __syncthreads();

    for (int tile = blockIdx.x; tile < ntiles; tile += gridDim.x) {
        int block_row = tile * 128;

        // ---- A tile: 128 rows, 4 threads per row (32 cols each) ----
        {
            int r = tid >> 2, q = tid & 3;
            int grow = block_row + r;
            uint32_t dbase = (uint32_t)r * (APITCH * 2) + q * 64;
            if (MODE == 0) {
                const uint4* srch = Ahi + (size_t)grow * 16 + q * 4;
                const uint4* srcl = Alo + (size_t)grow * 16 + q * 4;
#pragma unroll
                for (int i = 0; i < 4; i++) {
                    uint4 vh, vl;
                    if (grow < nrows) {
                        vh = __ldg(&srch[i]);
                        vl = __ldg(&srcl[i]);
                    } else {
                        vh = make_uint4(0, 0, 0, 0);
                        vl = make_uint4(0, 0, 0, 0);
                    }
                    *reinterpret_cast<uint4*>(smem + SM_AHI + dbase + i * 16) = vh;
                    *reinterpret_cast<uint4*>(smem + SM_ALO + dbase + i * 16) = vl;
                }
            } else {
                const float4* arow =
                    reinterpret_cast<const float4*>(Af32 + (size_t)grow * HH + q * 32);
#pragma unroll
                for (int i = 0; i < 4; i++) {
                    float v[8];
                    if (grow < nrows) {
                        float4 p0 = arow[2 * i], p1 = arow[2 * i + 1];
                        v[0] = p0.x; v[1] = p0.y; v[2] = p0.z; v[3] = p0.w;
                        v[4] = p1.x; v[5] = p1.y; v[6] = p1.z; v[7] = p1.w;
                        int c0 = q * 32 + i * 8;
#pragma unroll
                        for (int j = 0; j < 8; j++)
                            v[j] = fmaxf(fmaf(v[j], sh_scale[c0 + j], sh_shift[c0 + j]), 0.f);
                    } else {
#pragma unroll
                        for (int j = 0; j < 8; j++) v[j] = 0.f;
                    }
                    uint32_t hi[4], lo[4];
#pragma unroll
                    for (int j = 0; j < 4; j++)
                        split_bf16x2(v[2 * j], v[2 * j + 1], hi[j], lo[j]);
                    *reinterpret_cast<uint4*>(smem + SM_AHI + dbase + i * 16) =
                        make_uint4(hi[0], hi[1], hi[2], hi[3]);
                    *reinterpret_cast<uint4*>(smem + SM_ALO + dbase + i * 16) =
                        make_uint4(lo[0], lo[1], lo[2], lo[3]);
                }
            }
        }
        __syncthreads();

        // ---- mainloop: 8 k-steps of 16; 3 terms (hh, hl, lh) ----
        float acc[2][4][4] = {};
#pragma unroll
        for (int ks = 0; ks < 8; ks++) {
            uint32_t kb = (uint32_t)ks * 32 + tig * 4;
            uint32_t ah[2][4], al[2][4], bh[4][2], bl[4][2];
#pragma unroll
            for (int mf = 0; mf < 2; mf++) {
                uint32_t base = (uint32_t)(warp_m * 32 + mf * 16 + groupID) * (APITCH * 2) + kb;
                ah[mf][0] = *(const uint32_t*)(smem + SM_AHI + base);
                ah[mf][1] = *(const uint32_t*)(smem + SM_AHI + base + 8 * APITCH * 2);
                ah[mf][2] = *(const uint32_t*)(smem + SM_AHI + base + 16);
                ah[mf][3] = *(const uint32_t*)(smem + SM_AHI + base + 8 * APITCH * 2 + 16);
                al[mf][0] = *(const uint32_t*)(smem + SM_ALO + base);
                al[mf][1] = *(const uint32_t*)(smem + SM_ALO + base + 8 * APITCH * 2);
                al[mf][2] = *(const uint32_t*)(smem + SM_ALO + base + 16);
                al[mf][3] = *(const uint32_t*)(smem + SM_ALO + base + 8 * APITCH * 2 + 16);
            }
#pragma unroll
            for (int nf = 0; nf < 4; nf++) {
                uint32_t base = (uint32_t)(warp_n * 32 + nf * 8 + groupID) * (APITCH * 2) + kb;
                bh[nf][0] = *(const uint32_t*)(smem + SM_BHI + base);
                bh[nf][1] = *(const uint32_t*)(smem + SM_BHI + base + 16);
                bl[nf][0] = *(const uint32_t*)(smem + SM_BLO + base);
                bl[nf][1] = *(const uint32_t*)(smem + SM_BLO + base + 16);
            }
#pragma unroll
            for (int mf = 0; mf < 2; mf++)
#pragma unroll
                for (int nf = 0; nf < 4; nf++) {
                    mma16816(acc[mf][nf], ah[mf], bh[nf]);
                    mma16816(acc[mf][nf], ah[mf], bl[nf]);
                    mma16816(acc[mf][nf], al[mf], bh[nf]);
                }
        }

        // ---- epilogue ----
        float cs[4][2] = {}, cq[4][2] = {};
#pragma unroll
        for (int mf = 0; mf < 2; mf++) {
            int r0 = block_row + warp_m * 32 + mf * 16 + groupID;
            int r1 = r0 + 8;
#pragma unroll
            for (int nf = 0; nf < 4; nf++) {
                int c0 = warp_n * 32 + nf * 8 + 2 * tig;
                float b0 = sh_bias[c0], b1 = sh_bias[c0 + 1];
                float t00 = acc[mf][nf][0] + b0, t01 = acc[mf][nf][1] + b1;
                float t10 = acc[mf][nf][2] + b0, t11 = acc[mf][nf][3] + b1;
                if (MODE == 1) {
                    t00 = fmaxf(t00, 0.f); t01 = fmaxf(t01, 0.f);
                    t10 = fmaxf(t10, 0.f); t11 = fmaxf(t11, 0.f);
                }
                if (r0 < nrows) {
                    *reinterpret_cast<float2*>(out + (size_t)r0 * HH + c0) =
                        make_float2(t00, t01);
                    if (MODE == 0) {
                        cs[nf][0] += t00; cq[nf][0] = fmaf(t00, t00, cq[nf][0]);
                        cs[nf][1] += t01; cq[nf][1] = fmaf(t01, t01, cq[nf][1]);
                    }
                }
                if (r1 < nrows) {
                    *reinterpret_cast<float2*>(out + (size_t)r1 * HH + c0) =
                        make_float2(t10, t11);
                    if (MODE == 0) {
                        cs[nf][0] += t10; cq[nf][0] = fmaf(t10, t10, cq[nf][0]);
                        cs[nf][1] += t11; cq[nf][1] = fmaf(t11, t11, cq[nf][1]);
                    }
                }
            }
        }
        if (MODE == 0) {
#pragma unroll
            for (int nf = 0; nf < 4; nf++)
#pragma unroll
                for (int j = 0; j < 2; j++) {
                    float s = cs[nf][j], q = cq[nf][j];
#pragma unroll
                    for (int off = 16; off >= 4; off >>= 1) {
                        s += __shfl_down_sync(0xffffffff, s, off);
                        q += __shfl_down_sync(0xffffffff, q, off);
                    }
                    if (lane < 4) {
                        int col = warp_n * 32 + nf * 8 + 2 * lane + j;
                        atomicAdd(&g_stats[col], s);
                        atomicAdd(&g_stats[128 + col], q);
                    }
                }
        }
        __syncthreads();   // A smem reusable next tile
    }
}

// ---------------- segment-CSR readout ----------------
__global__ void readout_kernel(const float* __restrict__ h,
                               const int* __restrict__ ptr,
                               float* __restrict__ out) {
    int g = blockIdx.x;
    int c = threadIdx.x;
    int s = ptr[g], e = ptr[g + 1];
    float acc = 0.f;
    for (int r = s; r < e; r++) acc += h[r * HH + c];
    out[g * HH + c] = acc;
}

// ---------------- host launch ----------------
extern "C" void kernel_launch(void* const* d_in, const int* in_sizes, int n_in,
                              void* d_out, int out_size) {
    const float* x = (const float*)d_in[0];
    const int* src = (const int*)d_in[1];
    const int* dst = (const int*)d_in[2];
    const int* ptr = (const int*)d_in[3];
    int E = in_sizes[1];
    int N = in_sizes[0] / HH;
    int G = in_sizes[3] - 1;
    float* out = (float*)d_out;

    float *z, *hA, *hB;
    int *deg, *slot, *rowstart, *csr;
    uint2 *ahi, *alo;
    unsigned short* wimg;
    cudaGetSymbolAddress((void**)&z, g_z);
    cudaGetSymbolAddress((void**)&hA, g_hA);
    cudaGetSymbolAddress((void**)&hB, g_hB);
    cudaGetSymbolAddress((void**)&deg, g_deg);
    cudaGetSymbolAddress((void**)&slot, g_slot);
    cudaGetSymbolAddress((void**)&rowstart, g_rowstart);
    cudaGetSymbolAddress((void**)&csr, g_csr);
    cudaGetSymbolAddress((void**)&ahi, g_ahi);
    cudaGetSymbolAddress((void**)&alo, g_alo);
    cudaGetSymbolAddress((void**)&wimg, g_w);

    cudaFuncSetAttribute(gemm_mma<0>, cudaFuncAttributeMaxDynamicSharedMemorySize, SM_TOTAL);
    cudaFuncSetAttribute(gemm_mma<1>, cudaFuncAttributeMaxDynamicSharedMemorySize, SM_TOTAL);

    int ntiles = (N + 127) / 128;
    int gemm_grid = ntiles < 148 ? ntiles : 148;
    int eb = (E + 255) / 256;
    int agg_blocks = (int)(((long long)N * 32 + 255) / 256);
    float inv_n = 1.0f / (float)N;

    int zero_blocks = (N + 255) / 256;
    prep_kernel<<<384 + zero_blocks, 256>>>(
        (const float*)d_in[4], (const float*)d_in[8],
        (const float*)d_in[10], (const float*)d_in[14],
        (const float*)d_in[16], (const float*)d_in[20], N);
    count_kernel<<<eb, 256>>>(dst, deg, slot, E);
    scan_kernel<<<1, 1024>>>(deg, rowstart, N);
    fill_kernel<<<eb, 256>>>(src, dst, rowstart, slot, csr, E);

    auto layer = [&](const float* hin, float* hout, int li) {
        int base = 4 + 6 * li;
        const float* ba = (const float*)d_in[base + 1];
        const float* ga = (const float*)d_in[base + 2];
        const float* be = (const float*)d_in[base + 3];
        const float* bb = (const float*)d_in[base + 5];
        const uint4* wahi = (const uint4*)(wimg + (size_t)(4 * li + 0) * WIMG_ELEMS);
        const uint4* walo = (const uint4*)(wimg + (size_t)(4 * li + 1) * WIMG_ELEMS);
        const uint4* wbhi = (const uint4*)(wimg + (size_t)(4 * li + 2) * WIMG_ELEMS);
        const uint4* wblo = (const uint4*)(wimg + (size_t)(4 * li + 3) * WIMG_ELEMS);

        aggregate_kernel<<<agg_blocks, 256>>>((const float4*)hin, rowstart, csr,
                                              ahi, alo, N);
        gemm_mma<0><<<gemm_grid, 512, SM_TOTAL>>>(
            nullptr, (const uint4*)ahi, (const uint4*)alo, wahi, walo,
            ba, nullptr, nullptr, 0.f, z, N, ntiles);
        gemm_mma<1><<<gemm_grid, 512, SM_TOTAL>>>(
            z, nullptr, nullptr, wbhi, wblo,
            bb, ga, be, inv_n, hout, N, ntiles);
    };

    layer(x, hA, 0);
    layer(hA, hB, 1);
    layer(hB, hA, 2);

    readout_kernel<<<G, 128>>>(hA, ptr, out);
}

// round 12
// speedup vs baseline: 1.1217x; 1.1217x over previous
#include <cuda_runtime.h>
#include <cuda_bf16.h>
#include <cstdint>

#define HH 128
#define NMAX 50000
#define EMAX 800000
#define BN_EPS 1e-5f
#define APITCH 136
#define WIMG_ELEMS (128 * APITCH)

// ---------------- scratch (no allocations allowed) ----------------
__device__ float g_z[NMAX * HH];
__device__ float g_hA[NMAX * HH];
__device__ float g_hB[NMAX * HH];
__device__ float g_stats[2 * HH];
__device__ int   g_deg[NMAX];
__device__ int   g_slot[EMAX];
__device__ int   g_rowstart[NMAX + 1];
__device__ int   g_csr[EMAX];
__device__ uint2 g_ahi[NMAX * 32];
__device__ uint2 g_alo[NMAX * 32];
__device__ unsigned short g_w[12][WIMG_ELEMS];

// ---------------- prep: all 6 W conversions + zero deg/stats ----------
__global__ void prep_kernel(const float* __restrict__ w0, const float* __restrict__ w1,
                            const float* __restrict__ w2, const float* __restrict__ w3,
                            const float* __restrict__ w4, const float* __restrict__ w5,
                            int N) {
    int b = blockIdx.x;
    int tid = threadIdx.x;
    if (b < 384) {
        int wi = b >> 6;
        int i = ((b & 63) << 8) + tid;
        const float* W;
        switch (wi) {
            case 0: W = w0; break;
            case 1: W = w1; break;
            case 2: W = w2; break;
            case 3: W = w3; break;
            case 4: W = w4; break;
            default: W = w5; break;
        }
        int k = i >> 7, n = i & 127;
        float v = __ldg(&W[i]);
        __nv_bfloat16 h = __float2bfloat16_rn(v);
        __nv_bfloat16 l = __float2bfloat16_rn(v - __bfloat162float(h));
        g_w[2 * wi + 0][n * APITCH + k] = __bfloat16_as_ushort(h);
        g_w[2 * wi + 1][n * APITCH + k] = __bfloat16_as_ushort(l);
    } else {
        int idx = (b - 384) * 256 + tid;
        if (idx < N) g_deg[idx] = 0;
        if (b == 384 && tid < 256) g_stats[tid] = 0.f;
    }
}

// ---------------- CSR build ----------------
__global__ void count_kernel(const int* __restrict__ dst, int* __restrict__ deg,
                             int* __restrict__ slot, int E) {
    int e = blockIdx.x * blockDim.x + threadIdx.x;
    if (e < E) slot[e] = atomicAdd(&deg[dst[e]], 1);
}

__global__ void scan_kernel(const int* __restrict__ deg, int* __restrict__ rowstart, int n) {
    __shared__ int warpsum[32];
    __shared__ int s_total;
    __shared__ int s_carry;
    int tid = threadIdx.x, lane = tid & 31, wid = tid >> 5;
    if (tid == 0) s_carry = 0;
    __syncthreads();
    for (int base = 0; base < n; base += 1024) {
        int i = base + tid;
        int v = (i < n) ? deg[i] : 0;
        int incl = v;
#pragma unroll
        for (int off = 1; off < 32; off <<= 1) {
            int t = __shfl_up_sync(0xffffffff, incl, off);
            if (lane >= off) incl += t;
        }
        if (lane == 31) warpsum[wid] = incl;
        __syncthreads();
        if (wid == 0) {
            int w = warpsum[lane];
            int wincl = w;
#pragma unroll
            for (int off = 1; off < 32; off <<= 1) {
                int t = __shfl_up_sync(0xffffffff, wincl, off);
                if (lane >= off) wincl += t;
            }
            warpsum[lane] = wincl - w;
            if (lane == 31) s_total = wincl;
        }
        __syncthreads();
        int carry = s_carry;
        if (i < n) rowstart[i] = carry + warpsum[wid] + incl - v;
        __syncthreads();
        if (tid == 0) s_carry = carry + s_total;
    }
    __syncthreads();
    if (tid == 0) rowstart[n] = s_carry;
}

__global__ void fill_kernel(const int* __restrict__ src, const int* __restrict__ dst,
                            const int* __restrict__ rowstart, const int* __restrict__ slot,
                            int* __restrict__ csr, int E) {
    int e = blockIdx.x * blockDim.x + threadIdx.x;
    if (e >= E) return;
    int d = dst[e];
    csr[__ldg(&rowstart[d]) + slot[e]] = src[e];
}

// ---------------- aggregate -> bf16 hi/lo planes; block 0 zeroes stats -------
__global__ void aggregate_kernel(const float4* __restrict__ h,
                                 const int* __restrict__ rowstart,
                                 const int* __restrict__ csr,
                                 uint2* __restrict__ ahi,
                                 uint2* __restrict__ alo, int N) {
    if (blockIdx.x == 0 && threadIdx.x < 256) g_stats[threadIdx.x] = 0.f;
    int warp = (blockIdx.x * blockDim.x + threadIdx.x) >> 5;
    int lane = threadIdx.x & 31;
    if (warp >= N) return;
    int s0 = rowstart[warp], s1 = rowstart[warp + 1];
    float4 acc = __ldg(&h[(size_t)warp * 32 + lane]);
    int j = s0;
    for (; j + 2 <= s1; j += 2) {
        int sa = __ldg(&csr[j]);
        int sb = __ldg(&csr[j + 1]);
        float4 va = __ldg(&h[(size_t)sa * 32 + lane]);
        float4 vb = __ldg(&h[(size_t)sb * 32 + lane]);
        acc.x += va.x + vb.x; acc.y += va.y + vb.y;
        acc.z += va.z + vb.z; acc.w += va.w + vb.w;
    }
    if (j < s1) {
        int sa = __ldg(&csr[j]);
        float4 va = __ldg(&h[(size_t)sa * 32 + lane]);
        acc.x += va.x; acc.y += va.y; acc.z += va.z; acc.w += va.w;
    }
    float v[4] = {acc.x, acc.y, acc.z, acc.w};
    uint32_t hi[2], lo[2];
#pragma unroll
    for (int p = 0; p < 2; p++) {
        __nv_bfloat16 h0 = __float2bfloat16_rn(v[2 * p]);
        __nv_bfloat16 h1 = __float2bfloat16_rn(v[2 * p + 1]);
        __nv_bfloat16 l0 = __float2bfloat16_rn(v[2 * p] - __bfloat162float(h0));
        __nv_bfloat16 l1 = __float2bfloat16_rn(v[2 * p + 1] - __bfloat162float(h1));
        hi[p] = (uint32_t)__bfloat16_as_ushort(h0) | ((uint32_t)__bfloat16_as_ushort(h1) << 16);
        lo[p] = (uint32_t)__bfloat16_as_ushort(l0) | ((uint32_t)__bfloat16_as_ushort(l1) << 16);
    }
    ahi[(size_t)warp * 32 + lane] = make_uint2(hi[0], hi[1]);
    alo[(size_t)warp * 32 + lane] = make_uint2(lo[0], lo[1]);
}

// ---------------- HMMA GEMM: BM=128, 256 threads (2x4 warps), persistent -----
#define PLANE_BYTES (128 * APITCH * 2)   // 34816
#define SM_SCALE 0
#define SM_SHIFT 512
#define SM_BIAS  1024
#define SM_AHI   1536
#define SM_ALO   (SM_AHI + PLANE_BYTES)
#define SM_BHI   (SM_ALO + PLANE_BYTES)
#define SM_BLO   (SM_BHI + PLANE_BYTES)
#define SM_TOTAL (SM_BLO + PLANE_BYTES)  // 140800

__device__ __forceinline__ void mma16816(float* d, const uint32_t* a, const uint32_t* b) {
    asm volatile(
        "mma.sync.aligned.m16n8k16.row.col.f32.bf16.bf16.f32 "
        "{%0,%1,%2,%3}, {%4,%5,%6,%7}, {%8,%9}, {%0,%1,%2,%3};"
        : "+f"(d[0]), "+f"(d[1]), "+f"(d[2]), "+f"(d[3])
        : "r"(a[0]), "r"(a[1]), "r"(a[2]), "r"(a[3]), "r"(b[0]), "r"(b[1]));
}

__device__ __forceinline__ void split_bf16x2(float a0, float a1,
                                             uint32_t& hi, uint32_t& lo) {
    __nv_bfloat16 h0 = __float2bfloat16_rn(a0);
    __nv_bfloat16 h1 = __float2bfloat16_rn(a1);
    __nv_bfloat16 l0 = __float2bfloat16_rn(a0 - __bfloat162float(h0));
    __nv_bfloat16 l1 = __float2bfloat16_rn(a1 - __bfloat162float(h1));
    hi = (uint32_t)__bfloat16_as_ushort(h0) | ((uint32_t)__bfloat16_as_ushort(h1) << 16);
    lo = (uint32_t)__bfloat16_as_ushort(l0) | ((uint32_t)__bfloat16_as_ushort(l1) << 16);
}

// MODE 0: A from preconverted planes; out=z; fused BN stats
// MODE 1: A = relu(z*scale+shift); out = relu(.)
template <int MODE>
__global__ __launch_bounds__(256, 1) void gemm_mma(
    const float* __restrict__ Af32,
    const uint4* __restrict__ Ahi, const uint4* __restrict__ Alo,
    const uint4* __restrict__ Whi, const uint4* __restrict__ Wlo,
    const float* __restrict__ bias, const float* __restrict__ gamma,
    const float* __restrict__ beta, float inv_n,
    float* __restrict__ out, int nrows, int ntiles) {
    extern __shared__ char smem[];
    int tid = threadIdx.x;
    int lane = tid & 31;
    int wid = tid >> 5;
    int groupID = lane >> 2;
    int tig = lane & 3;
    int warp_m = wid & 1;
    int warp_n = wid >> 1;

    float* sh_scale = (float*)(smem + SM_SCALE);
    float* sh_shift = (float*)(smem + SM_SHIFT);
    float* sh_bias  = (float*)(smem + SM_BIAS);

    // ---- once per CTA: bias/scale + W planes ----
    if (tid < 128) {
        sh_bias[tid] = bias[tid];
        if (MODE == 1) {
            float mu = g_stats[tid] * inv_n;
            float var = fmaf(-mu, mu, g_stats[128 + tid] * inv_n);
            float rs = rsqrtf(var + BN_EPS);
            float sc = gamma[tid] * rs;
            sh_scale[tid] = sc;
            sh_shift[tid] = fmaf(-mu, sc, beta[tid]);
        }
    }
    {
        uint4* dh = (uint4*)(smem + SM_BHI);
        uint4* dl = (uint4*)(smem + SM_BLO);
        for (int i = tid; i < PLANE_BYTES / 16; i += 256) {
            dh[i] = __ldg(&Whi[i]);
            dl[i] = __ldg(&Wlo[i]);
        }
    }
    if (MODE == 1) __syncthreads();

    for (int tile = blockIdx.x; tile < ntiles; tile += gridDim.x) {
        int block_row = tile * 128;

        // ---- A tile ----
        if (MODE == 0) {
            int r = tid >> 1, half = tid & 1;
            int grow = block_row + r;
            uint32_t dbase = (uint32_t)r * (APITCH * 2) + half * 128;
            const uint4* srch = Ahi + (size_t)grow * 16 + half * 8;
            const uint4* srcl = Alo + (size_t)grow * 16 + half * 8;
#pragma unroll
            for (int i = 0; i < 8; i++) {
                uint4 vh, vl;
                if (grow < nrows) {
                    vh = __ldg(&srch[i]);
                    vl = __ldg(&srcl[i]);
                } else {
                    vh = make_uint4(0, 0, 0, 0);
                    vl = make_uint4(0, 0, 0, 0);
                }
                *reinterpret_cast<uint4*>(smem + SM_AHI + dbase + i * 16) = vh;
                *reinterpret_cast<uint4*>(smem + SM_ALO + dbase + i * 16) = vl;
            }
        } else {
            int r = tid >> 1, half = tid & 1;
            int grow = block_row + r;
            const float4* arow =
                reinterpret_cast<const float4*>(Af32 + (size_t)grow * HH + half * 64);
            uint32_t dbase = (uint32_t)r * (APITCH * 2) + half * 128;
#pragma unroll
            for (int i = 0; i < 8; i++) {
                float v[8];
                if (grow < nrows) {
                    float4 p0 = arow[2 * i], p1 = arow[2 * i + 1];
                    v[0] = p0.x; v[1] = p0.y; v[2] = p0.z; v[3] = p0.w;
                    v[4] = p1.x; v[5] = p1.y; v[6] = p1.z; v[7] = p1.w;
                    int c0 = half * 64 + i * 8;
#pragma unroll
                    for (int j = 0; j < 8; j++)
                        v[j] = fmaxf(fmaf(v[j], sh_scale[c0 + j], sh_shift[c0 + j]), 0.f);
                } else {
#pragma unroll
                    for (int j = 0; j < 8; j++) v[j] = 0.f;
                }
                uint32_t hi[4], lo[4];
#pragma unroll
                for (int j = 0; j < 4; j++)
                    split_bf16x2(v[2 * j], v[2 * j + 1], hi[j], lo[j]);
                uint32_t off = dbase + i * 16;
                *reinterpret_cast<uint4*>(smem + SM_AHI + off) =
                    make_uint4(hi[0], hi[1], hi[2], hi[3]);
                *reinterpret_cast<uint4*>(smem + SM_ALO + off) =
                    make_uint4(lo[0], lo[1], lo[2], lo[3]);
            }
        }
        __syncthreads();

        // ---- mainloop: 8 k-steps of 16; TERM-MAJOR (hh pass, hl pass, lh pass)
        float acc[4][4][4] = {};
#pragma unroll
        for (int ks = 0; ks < 8; ks++) {
            uint32_t kb = (uint32_t)ks * 32 + tig * 4;
            uint32_t ah[4][4], al[4][4], bh[4][2], bl[4][2];
#pragma unroll
            for (int mf = 0; mf < 4; mf++) {
                uint32_t base = (uint32_t)(warp_m * 64 + mf * 16 + groupID) * (APITCH * 2) + kb;
                ah[mf][0] = *(const uint32_t*)(smem + SM_AHI + base);
                ah[mf][1] = *(const uint32_t*)(smem + SM_AHI + base + 8 * APITCH * 2);
                ah[mf][2] = *(const uint32_t*)(smem + SM_AHI + base + 16);
                ah[mf][3] = *(const uint32_t*)(smem + SM_AHI + base + 8 * APITCH * 2 + 16);
                al[mf][0] = *(const uint32_t*)(smem + SM_ALO + base);
                al[mf][1] = *(const uint32_t*)(smem + SM_ALO + base + 8 * APITCH * 2);
                al[mf][2] = *(const uint32_t*)(smem + SM_ALO + base + 16);
                al[mf][3] = *(const uint32_t*)(smem + SM_ALO + base + 8 * APITCH * 2 + 16);
            }
#pragma unroll
            for (int nf = 0; nf < 4; nf++) {
                uint32_t base = (uint32_t)(warp_n * 32 + nf * 8 + groupID) * (APITCH * 2) + kb;
                bh[nf][0] = *(const uint32_t*)(smem + SM_BHI + base);
                bh[nf][1] = *(const uint32_t*)(smem + SM_BHI + base + 16);
                bl[nf][0] = *(const uint32_t*)(smem + SM_BLO + base);
                bl[nf][1] = *(const uint32_t*)(smem + SM_BLO + base + 16);
            }
            // pass 1: hi*hi — 16 independent HMMAs
#pragma unroll
            for (int mf = 0; mf < 4; mf++)
#pragma unroll
                for (int nf = 0; nf < 4; nf++)
                    mma16816(acc[mf][nf], ah[mf], bh[nf]);
            // pass 2: hi*lo — each acc 16 ops after its last write
#pragma unroll
            for (int mf = 0; mf < 4; mf++)
#pragma unroll
                for (int nf = 0; nf < 4; nf++)
                    mma16816(acc[mf][nf], ah[mf], bl[nf]);
            // pass 3: lo*hi
#pragma unroll
            for (int mf = 0; mf < 4; mf++)
#pragma unroll
                for (int nf = 0; nf < 4; nf++)
                    mma16816(acc[mf][nf], al[mf], bh[nf]);
        }

        // ---- epilogue ----
        float cs[4][2] = {}, cq[4][2] = {};
#pragma unroll
        for (int mf = 0; mf < 4; mf++) {
            int r0 = block_row + warp_m * 64 + mf * 16 + groupID;
            int r1 = r0 + 8;
#pragma unroll
            for (int nf = 0; nf < 4; nf++) {
                int c0 = warp_n * 32 + nf * 8 + 2 * tig;
                float b0 = sh_bias[c0], b1 = sh_bias[c0 + 1];
                float t00 = acc[mf][nf][0] + b0, t01 = acc[mf][nf][1] + b1;
                float t10 = acc[mf][nf][2] + b0, t11 = acc[mf][nf][3] + b1;
                if (MODE == 1) {
                    t00 = fmaxf(t00, 0.f); t01 = fmaxf(t01, 0.f);
                    t10 = fmaxf(t10, 0.f); t11 = fmaxf(t11, 0.f);
                }
                if (r0 < nrows) {
                    *reinterpret_cast<float2*>(out + (size_t)r0 * HH + c0) =
                        make_float2(t00, t01);
                    if (MODE == 0) {
                        cs[nf][0] += t00; cq[nf][0] = fmaf(t00, t00, cq[nf][0]);
                        cs[nf][1] += t01; cq[nf][1] = fmaf(t01, t01, cq[nf][1]);
                    }
                }
                if (r1 < nrows) {
                    *reinterpret_cast<float2*>(out + (size_t)r1 * HH + c0) =
                        make_float2(t10, t11);
                    if (MODE == 0) {
                        cs[nf][0] += t10; cq[nf][0] = fmaf(t10, t10, cq[nf][0]);
                        cs[nf][1] += t11; cq[nf][1] = fmaf(t11, t11, cq[nf][1]);
                    }
                }
            }
        }
        if (MODE == 0) {
#pragma unroll
            for (int nf = 0; nf < 4; nf++)
#pragma unroll
                for (int j = 0; j < 2; j++) {
                    float s = cs[nf][j], q = cq[nf][j];
#pragma unroll
                    for (int off = 16; off >= 4; off >>= 1) {
                        s += __shfl_down_sync(0xffffffff, s, off);
                        q += __shfl_down_sync(0xffffffff, q, off);
                    }
                    if (lane < 4) {
                        int col = warp_n * 32 + nf * 8 + 2 * lane + j;
                        atomicAdd(&g_stats[col], s);
                        atomicAdd(&g_stats[128 + col], q);
                    }
                }
        }
        __syncthreads();   // A smem reusable next tile
    }
}

// ---------------- segment-CSR readout ----------------
__global__ void readout_kernel(const float* __restrict__ h,
                               const int* __restrict__ ptr,
                               float* __restrict__ out) {
    int g = blockIdx.x;
    int c = threadIdx.x;
    int s = ptr[g], e = ptr[g + 1];
    float acc = 0.f;
    for (int r = s; r < e; r++) acc += h[r * HH + c];
    out[g * HH + c] = acc;
}

// ---------------- host launch ----------------
extern "C" void kernel_launch(void* const* d_in, const int* in_sizes, int n_in,
                              void* d_out, int out_size) {
    const float* x = (const float*)d_in[0];
    const int* src = (const int*)d_in[1];
    const int* dst = (const int*)d_in[2];
    const int* ptr = (const int*)d_in[3];
    int E = in_sizes[1];
    int N = in_sizes[0] / HH;
    int G = in_sizes[3] - 1;
    float* out = (float*)d_out;

    float *z, *hA, *hB;
    int *deg, *slot, *rowstart, *csr;
    uint2 *ahi, *alo;
    unsigned short* wimg;
    cudaGetSymbolAddress((void**)&z, g_z);
    cudaGetSymbolAddress((void**)&hA, g_hA);
    cudaGetSymbolAddress((void**)&hB, g_hB);
    cudaGetSymbolAddress((void**)&deg, g_deg);
    cudaGetSymbolAddress((void**)&slot, g_slot);
    cudaGetSymbolAddress((void**)&rowstart, g_rowstart);
    cudaGetSymbolAddress((void**)&csr, g_csr);
    cudaGetSymbolAddress((void**)&ahi, g_ahi);
    cudaGetSymbolAddress((void**)&alo, g_alo);
    cudaGetSymbolAddress((void**)&wimg, g_w);

    cudaFuncSetAttribute(gemm_mma<0>, cudaFuncAttributeMaxDynamicSharedMemorySize, SM_TOTAL);
    cudaFuncSetAttribute(gemm_mma<1>, cudaFuncAttributeMaxDynamicSharedMemorySize, SM_TOTAL);

    int ntiles = (N + 127) / 128;
    int gemm_grid = ntiles < 148 ? ntiles : 148;
    int eb = (E + 255) / 256;
    int agg_blocks = (int)(((long long)N * 32 + 255) / 256);
    float inv_n = 1.0f / (float)N;

    int zero_blocks = (N + 255) / 256;
    prep_kernel<<<384 + zero_blocks, 256>>>(
        (const float*)d_in[4], (const float*)d_in[8],
        (const float*)d_in[10], (const float*)d_in[14],
        (const float*)d_in[16], (const float*)d_in[20], N);
    count_kernel<<<eb, 256>>>(dst, deg, slot, E);
    scan_kernel<<<1, 1024>>>(deg, rowstart, N);
    fill_kernel<<<eb, 256>>>(src, dst, rowstart, slot, csr, E);

    auto layer = [&](const float* hin, float* hout, int li) {
        int base = 4 + 6 * li;
        const float* ba = (const float*)d_in[base + 1];
        const float* ga = (const float*)d_in[base + 2];
        const float* be = (const float*)d_in[base + 3];
        const float* bb = (const float*)d_in[base + 5];
        const uint4* wahi = (const uint4*)(wimg + (size_t)(4 * li + 0) * WIMG_ELEMS);
        const uint4* walo = (const uint4*)(wimg + (size_t)(4 * li + 1) * WIMG_ELEMS);
        const uint4* wbhi = (const uint4*)(wimg + (size_t)(4 * li + 2) * WIMG_ELEMS);
        const uint4* wblo = (const uint4*)(wimg + (size_t)(4 * li + 3) * WIMG_ELEMS);

        aggregate_kernel<<<agg_blocks, 256>>>((const float4*)hin, rowstart, csr,
                                              ahi, alo, N);
        gemm_mma<0><<<gemm_grid, 256, SM_TOTAL>>>(
            nullptr, (const uint4*)ahi, (const uint4*)alo, wahi, walo,
            ba, nullptr, nullptr, 0.f, z, N, ntiles);
        gemm_mma<1><<<gemm_grid, 256, SM_TOTAL>>>(
            z, nullptr, nullptr, wbhi, wblo,
            bb, ga, be, inv_n, hout, N, ntiles);
    };

    layer(x, hA, 0);
    layer(hA, hB, 1);
    layer(hB, hA, 2);

    readout_kernel<<<G, 128>>>(hA, ptr, out);
}

// round 14
// speedup vs baseline: 1.2081x; 1.0770x over previous
#include <cuda_runtime.h>
#include <cuda_fp16.h>
#include <cstdint>

#define HH 128
#define NMAX 50000
#define EMAX 800000
#define BN_EPS 1e-5f
#define APITCH 136
#define WIMG_ELEMS (128 * APITCH)

// ---------------- scratch (no allocations allowed) ----------------
__device__ float g_z[NMAX * HH];
__device__ float g_hA[NMAX * HH];
__device__ float g_hB[NMAX * HH];
__device__ float g_stats[2 * HH];
__device__ int   g_deg[NMAX];
__device__ int   g_slot[EMAX];
__device__ int   g_rowstart[NMAX + 1];
__device__ int   g_csr[EMAX];
__device__ uint2 g_ahi[NMAX * 32];
__device__ uint2 g_alo[NMAX * 32];
__device__ unsigned short g_w[6][WIMG_ELEMS];   // 6 weight matrices, single fp16 plane

// ---------------- prep: 6 W fp16 conversions + zero deg/stats ----------
__global__ void prep_kernel(const float* __restrict__ w0, const float* __restrict__ w1,
                            const float* __restrict__ w2, const float* __restrict__ w3,
                            const float* __restrict__ w4, const float* __restrict__ w5,
                            int N) {
    int b = blockIdx.x;
    int tid = threadIdx.x;
    if (b < 384) {
        int wi = b >> 6;
        int i = ((b & 63) << 8) + tid;
        const float* W;
        switch (wi) {
            case 0: W = w0; break;
            case 1: W = w1; break;
            case 2: W = w2; break;
            case 3: W = w3; break;
            case 4: W = w4; break;
            default: W = w5; break;
        }
        int k = i >> 7, n = i & 127;
        float v = __ldg(&W[i]);
        g_w[wi][n * APITCH + k] = __half_as_ushort(__float2half_rn(v));
    } else {
        int idx = (b - 384) * 256 + tid;
        if (idx < N) g_deg[idx] = 0;
        if (b == 384 && tid < 256) g_stats[tid] = 0.f;
    }
}

// ---------------- CSR build ----------------
__global__ void count_kernel(const int* __restrict__ dst, int* __restrict__ deg,
                             int* __restrict__ slot, int E) {
    int e = blockIdx.x * blockDim.x + threadIdx.x;
    if (e < E) slot[e] = atomicAdd(&deg[dst[e]], 1);
}

__global__ void scan_kernel(const int* __restrict__ deg, int* __restrict__ rowstart, int n) {
    __shared__ int warpsum[32];
    __shared__ int s_total;
    __shared__ int s_carry;
    int tid = threadIdx.x, lane = tid & 31, wid = tid >> 5;
    if (tid == 0) s_carry = 0;
    __syncthreads();
    for (int base = 0; base < n; base += 1024) {
        int i = base + tid;
        int v = (i < n) ? deg[i] : 0;
        int incl = v;
#pragma unroll
        for (int off = 1; off < 32; off <<= 1) {
            int t = __shfl_up_sync(0xffffffff, incl, off);
            if (lane >= off) incl += t;
        }
        if (lane == 31) warpsum[wid] = incl;
        __syncthreads();
        if (wid == 0) {
            int w = warpsum[lane];
            int wincl = w;
#pragma unroll
            for (int off = 1; off < 32; off <<= 1) {
                int t = __shfl_up_sync(0xffffffff, wincl, off);
                if (lane >= off) wincl += t;
            }
            warpsum[lane] = wincl - w;
            if (lane == 31) s_total = wincl;
        }
        __syncthreads();
        int carry = s_carry;
        if (i < n) rowstart[i] = carry + warpsum[wid] + incl - v;
        __syncthreads();
        if (tid == 0) s_carry = carry + s_total;
    }
    __syncthreads();
    if (tid == 0) rowstart[n] = s_carry;
}

__global__ void fill_kernel(const int* __restrict__ src, const int* __restrict__ dst,
                            const int* __restrict__ rowstart, const int* __restrict__ slot,
                            int* __restrict__ csr, int E) {
    int e = blockIdx.x * blockDim.x + threadIdx.x;
    if (e >= E) return;
    int d = dst[e];
    csr[__ldg(&rowstart[d]) + slot[e]] = src[e];
}

// ---------------- fp16 hi/lo split helpers ----------------
__device__ __forceinline__ void split_f16x2(float a0, float a1,
                                            uint32_t& hi, uint32_t& lo) {
    __half h0 = __float2half_rn(a0);
    __half h1 = __float2half_rn(a1);
    __half l0 = __float2half_rn(a0 - __half2float(h0));
    __half l1 = __float2half_rn(a1 - __half2float(h1));
    hi = (uint32_t)__half_as_ushort(h0) | ((uint32_t)__half_as_ushort(h1) << 16);
    lo = (uint32_t)__half_as_ushort(l0) | ((uint32_t)__half_as_ushort(l1) << 16);
}

// ---------------- aggregate -> fp16 hi/lo planes; block 0 zeroes stats -------
__global__ void aggregate_kernel(const float4* __restrict__ h,
                                 const int* __restrict__ rowstart,
                                 const int* __restrict__ csr,
                                 uint2* __restrict__ ahi,
                                 uint2* __restrict__ alo, int N) {
    if (blockIdx.x == 0 && threadIdx.x < 256) g_stats[threadIdx.x] = 0.f;
    int warp = (blockIdx.x * blockDim.x + threadIdx.x) >> 5;
    int lane = threadIdx.x & 31;
    if (warp >= N) return;
    int s0 = rowstart[warp], s1 = rowstart[warp + 1];
    float4 acc = __ldg(&h[(size_t)warp * 32 + lane]);
    int j = s0;
    for (; j + 2 <= s1; j += 2) {
        int sa = __ldg(&csr[j]);
        int sb = __ldg(&csr[j + 1]);
        float4 va = __ldg(&h[(size_t)sa * 32 + lane]);
        float4 vb = __ldg(&h[(size_t)sb * 32 + lane]);
        acc.x += va.x + vb.x; acc.y += va.y + vb.y;
        acc.z += va.z + vb.z; acc.w += va.w + vb.w;
    }
    if (j < s1) {
        int sa = __ldg(&csr[j]);
        float4 va = __ldg(&h[(size_t)sa * 32 + lane]);
        acc.x += va.x; acc.y += va.y; acc.z += va.z; acc.w += va.w;
    }
    uint32_t hi0, lo0, hi1, lo1;
    split_f16x2(acc.x, acc.y, hi0, lo0);
    split_f16x2(acc.z, acc.w, hi1, lo1);
    ahi[(size_t)warp * 32 + lane] = make_uint2(hi0, hi1);
    alo[(size_t)warp * 32 + lane] = make_uint2(lo0, lo1);
}

// ---------------- HMMA GEMM: fp16 2-term, BM=128, 256 thr, persistent --------
#define PLANE_BYTES (128 * APITCH * 2)   // 34816
#define SM_SCALE 0
#define SM_SHIFT 512
#define SM_BIAS  1024
#define SM_AHI   1536
#define SM_ALO   (SM_AHI + PLANE_BYTES)
#define SM_BW    (SM_ALO + PLANE_BYTES)
#define SM_TOTAL (SM_BW + PLANE_BYTES)   // 105984

__device__ __forceinline__ void mma16816(float* d, const uint32_t* a, const uint32_t* b) {
    asm volatile(
        "mma.sync.aligned.m16n8k16.row.col.f32.f16.f16.f32 "
        "{%0,%1,%2,%3}, {%4,%5,%6,%7}, {%8,%9}, {%0,%1,%2,%3};"
        : "+f"(d[0]), "+f"(d[1]), "+f"(d[2]), "+f"(d[3])
        : "r"(a[0]), "r"(a[1]), "r"(a[2]), "r"(a[3]), "r"(b[0]), "r"(b[1]));
}

// MODE 0: A from preconverted planes; out=z; fused BN stats
// MODE 1: A = relu(z*scale+shift); out = relu(.)
template <int MODE>
__global__ __launch_bounds__(256, 1) void gemm_mma(
    const float* __restrict__ Af32,
    const uint4* __restrict__ Ahi, const uint4* __restrict__ Alo,
    const uint4* __restrict__ Wimg,
    const float* __restrict__ bias, const float* __restrict__ gamma,
    const float* __restrict__ beta, float inv_n,
    float* __restrict__ out, int nrows, int ntiles) {
    extern __shared__ char smem[];
    int tid = threadIdx.x;
    int lane = tid & 31;
    int wid = tid >> 5;
    int groupID = lane >> 2;
    int tig = lane & 3;
    int warp_m = wid & 1;
    int warp_n = wid >> 1;

    float* sh_scale = (float*)(smem + SM_SCALE);
    float* sh_shift = (float*)(smem + SM_SHIFT);
    float* sh_bias  = (float*)(smem + SM_BIAS);

    // ---- once per CTA: bias/scale + W plane ----
    if (tid < 128) {
        sh_bias[tid] = bias[tid];
        if (MODE == 1) {
            float mu = g_stats[tid] * inv_n;
            float var = fmaf(-mu, mu, g_stats[128 + tid] * inv_n);
            float rs = rsqrtf(var + BN_EPS);
            float sc = gamma[tid] * rs;
            sh_scale[tid] = sc;
            sh_shift[tid] = fmaf(-mu, sc, beta[tid]);
        }
    }
    {
        uint4* dw = (uint4*)(smem + SM_BW);
        for (int i = tid; i < PLANE_BYTES / 16; i += 256)
            dw[i] = __ldg(&Wimg[i]);
    }
    if (MODE == 1) __syncthreads();

    for (int tile = blockIdx.x; tile < ntiles; tile += gridDim.x) {
        int block_row = tile * 128;

        // ---- A tile ----
        if (MODE == 0) {
            int r = tid >> 1, half = tid & 1;
            int grow = block_row + r;
            uint32_t dbase = (uint32_t)r * (APITCH * 2) + half * 128;
            const uint4* srch = Ahi + (size_t)grow * 16 + half * 8;
            const uint4* srcl = Alo + (size_t)grow * 16 + half * 8;
#pragma unroll
            for (int i = 0; i < 8; i++) {
                uint4 vh, vl;
                if (grow < nrows) {
                    vh = __ldg(&srch[i]);
                    vl = __ldg(&srcl[i]);
                } else {
                    vh = make_uint4(0, 0, 0, 0);
                    vl = make_uint4(0, 0, 0, 0);
                }
                *reinterpret_cast<uint4*>(smem + SM_AHI + dbase + i * 16) = vh;
                *reinterpret_cast<uint4*>(smem + SM_ALO + dbase + i * 16) = vl;
            }
        } else {
            int r = tid >> 1, half = tid & 1;
            int grow = block_row + r;
            const float4* arow =
                reinterpret_cast<const float4*>(Af32 + (size_t)grow * HH + half * 64);
            uint32_t dbase = (uint32_t)r * (APITCH * 2) + half * 128;
#pragma unroll
            for (int i = 0; i < 8; i++) {
                float v[8];
                if (grow < nrows) {
                    float4 p0 = arow[2 * i], p1 = arow[2 * i + 1];
                    v[0] = p0.x; v[1] = p0.y; v[2] = p0.z; v[3] = p0.w;
                    v[4] = p1.x; v[5] = p1.y; v[6] = p1.z; v[7] = p1.w;
                    int c0 = half * 64 + i * 8;
#pragma unroll
                    for (int j = 0; j < 8; j++)
                        v[j] = fmaxf(fmaf(v[j], sh_scale[c0 + j], sh_shift[c0 + j]), 0.f);
                } else {
#pragma unroll
                    for (int j = 0; j < 8; j++) v[j] = 0.f;
                }
                uint32_t hi[4], lo[4];
#pragma unroll
                for (int j = 0; j < 4; j++)
                    split_f16x2(v[2 * j], v[2 * j + 1], hi[j], lo[j]);
                uint32_t off = dbase + i * 16;
                *reinterpret_cast<uint4*>(smem + SM_AHI + off) =
                    make_uint4(hi[0], hi[1], hi[2], hi[3]);
                *reinterpret_cast<uint4*>(smem + SM_ALO + off) =
                    make_uint4(lo[0], lo[1], lo[2], lo[3]);
            }
        }
        __syncthreads();

        // ---- mainloop: 8 k-steps of 16; 2 terms (ah*w, al*w) ----
        float acc[4][4][4] = {};
#pragma unroll
        for (int ks = 0; ks < 8; ks++) {
            uint32_t kb = (uint32_t)ks * 32 + tig * 4;
            uint32_t ah[4][4], al[4][4], bw[4][2];
#pragma unroll
            for (int mf = 0; mf < 4; mf++) {
                uint32_t base = (uint32_t)(warp_m * 64 + mf * 16 + groupID) * (APITCH * 2) + kb;
                ah[mf][0] = *(const uint32_t*)(smem + SM_AHI + base);
                ah[mf][1] = *(const uint32_t*)(smem + SM_AHI + base + 8 * APITCH * 2);
                ah[mf][2] = *(const uint32_t*)(smem + SM_AHI + base + 16);
                ah[mf][3] = *(const uint32_t*)(smem + SM_AHI + base + 8 * APITCH * 2 + 16);
                al[mf][0] = *(const uint32_t*)(smem + SM_ALO + base);
                al[mf][1] = *(const uint32_t*)(smem + SM_ALO + base + 8 * APITCH * 2);
                al[mf][2] = *(const uint32_t*)(smem + SM_ALO + base + 16);
                al[mf][3] = *(const uint32_t*)(smem + SM_ALO + base + 8 * APITCH * 2 + 16);
            }
#pragma unroll
            for (int nf = 0; nf < 4; nf++) {
                uint32_t base = (uint32_t)(warp_n * 32 + nf * 8 + groupID) * (APITCH * 2) + kb;
                bw[nf][0] = *(const uint32_t*)(smem + SM_BW + base);
                bw[nf][1] = *(const uint32_t*)(smem + SM_BW + base + 16);
            }
#pragma unroll
            for (int mf = 0; mf < 4; mf++)
#pragma unroll
                for (int nf = 0; nf < 4; nf++) {
                    mma16816(acc[mf][nf], ah[mf], bw[nf]);
                    mma16816(acc[mf][nf], al[mf], bw[nf]);
                }
        }

        // ---- epilogue ----
        float cs[4][2] = {}, cq[4][2] = {};
#pragma unroll
        for (int mf = 0; mf < 4; mf++) {
            int r0 = block_row + warp_m * 64 + mf * 16 + groupID;
            int r1 = r0 + 8;
#pragma unroll
            for (int nf = 0; nf < 4; nf++) {
                int c0 = warp_n * 32 + nf * 8 + 2 * tig;
                float b0 = sh_bias[c0], b1 = sh_bias[c0 + 1];
                float t00 = acc[mf][nf][0] + b0, t01 = acc[mf][nf][1] + b1;
                float t10 = acc[mf][nf][2] + b0, t11 = acc[mf][nf][3] + b1;
                if (MODE == 1) {
                    t00 = fmaxf(t00, 0.f); t01 = fmaxf(t01, 0.f);
                    t10 = fmaxf(t10, 0.f); t11 = fmaxf(t11, 0.f);
                }
                if (r0 < nrows) {
                    *reinterpret_cast<float2*>(out + (size_t)r0 * HH + c0) =
                        make_float2(t00, t01);
                    if (MODE == 0) {
                        cs[nf][0] += t00; cq[nf][0] = fmaf(t00, t00, cq[nf][0]);
                        cs[nf][1] += t01; cq[nf][1] = fmaf(t01, t01, cq[nf][1]);
                    }
                }
                if (r1 < nrows) {
                    *reinterpret_cast<float2*>(out + (size_t)r1 * HH + c0) =
                        make_float2(t10, t11);
                    if (MODE == 0) {
                        cs[nf][0] += t10; cq[nf][0] = fmaf(t10, t10, cq[nf][0]);
                        cs[nf][1] += t11; cq[nf][1] = fmaf(t11, t11, cq[nf][1]);
                    }
                }
            }
        }
        if (MODE == 0) {
#pragma unroll
            for (int nf = 0; nf < 4; nf++)
#pragma unroll
                for (int j = 0; j < 2; j++) {
                    float s = cs[nf][j], q = cq[nf][j];
#pragma unroll
                    for (int off = 16; off >= 4; off >>= 1) {
                        s += __shfl_down_sync(0xffffffff, s, off);
                        q += __shfl_down_sync(0xffffffff, q, off);
                    }
                    if (lane < 4) {
                        int col = warp_n * 32 + nf * 8 + 2 * lane + j;
                        atomicAdd(&g_stats[col], s);
                        atomicAdd(&g_stats[128 + col], q);
                    }
                }
        }
        __syncthreads();   // A smem reusable next tile
    }
}

// ---------------- segment-CSR readout ----------------
__global__ void readout_kernel(const float* __restrict__ h,
                               const int* __restrict__ ptr,
                               float* __restrict__ out) {
    int g = blockIdx.x;
    int c = threadIdx.x;
    int s = ptr[g], e = ptr[g + 1];
    float acc = 0.f;
    for (int r = s; r < e; r++) acc += h[r * HH + c];
    out[g * HH + c] = acc;
}

// ---------------- host launch ----------------
extern "C" void kernel_launch(void* const* d_in, const int* in_sizes, int n_in,
                              void* d_out, int out_size) {
    const float* x = (const float*)d_in[0];
    const int* src = (const int*)d_in[1];
    const int* dst = (const int*)d_in[2];
    const int* ptr = (const int*)d_in[3];
    int E = in_sizes[1];
    int N = in_sizes[0] / HH;
    int G = in_sizes[3] - 1;
    float* out = (float*)d_out;

    float *z, *hA, *hB;
    int *deg, *slot, *rowstart, *csr;
    uint2 *ahi, *alo;
    unsigned short* wimg;
    cudaGetSymbolAddress((void**)&z, g_z);
    cudaGetSymbolAddress((void**)&hA, g_hA);
    cudaGetSymbolAddress((void**)&hB, g_hB);
    cudaGetSymbolAddress((void**)&deg, g_deg);
    cudaGetSymbolAddress((void**)&slot, g_slot);
    cudaGetSymbolAddress((void**)&rowstart, g_rowstart);
    cudaGetSymbolAddress((void**)&csr, g_csr);
    cudaGetSymbolAddress((void**)&ahi, g_ahi);
    cudaGetSymbolAddress((void**)&alo, g_alo);
    cudaGetSymbolAddress((void**)&wimg, g_w);

    cudaFuncSetAttribute(gemm_mma<0>, cudaFuncAttributeMaxDynamicSharedMemorySize, SM_TOTAL);
    cudaFuncSetAttribute(gemm_mma<1>, cudaFuncAttributeMaxDynamicSharedMemorySize, SM_TOTAL);

    int ntiles = (N + 127) / 128;
    int gemm_grid = ntiles < 148 ? ntiles : 148;
    int eb = (E + 255) / 256;
    int agg_blocks = (int)(((long long)N * 32 + 255) / 256);
    float inv_n = 1.0f / (float)N;

    int zero_blocks = (N + 255) / 256;
    prep_kernel<<<384 + zero_blocks, 256>>>(
        (const float*)d_in[4], (const float*)d_in[8],
        (const float*)d_in[10], (const float*)d_in[14],
        (const float*)d_in[16], (const float*)d_in[20], N);
    count_kernel<<<eb, 256>>>(dst, deg, slot, E);
    scan_kernel<<<1, 1024>>>(deg, rowstart, N);
    fill_kernel<<<eb, 256>>>(src, dst, rowstart, slot, csr, E);

    auto layer = [&](const float* hin, float* hout, int li) {
        int base = 4 + 6 * li;
        const float* ba = (const float*)d_in[base + 1];
        const float* ga = (const float*)d_in[base + 2];
        const float* be = (const float*)d_in[base + 3];
        const float* bb = (const float*)d_in[base + 5];
        // prep arg order: w0=L0.wa, w1=L0.wb, w2=L1.wa, w3=L1.wb, w4=L2.wa, w5=L2.wb
        const uint4* wa_img = (const uint4*)(wimg + (size_t)(2 * li + 0) * WIMG_ELEMS);
        const uint4* wb_img = (const uint4*)(wimg + (size_t)(2 * li + 1) * WIMG_ELEMS);

        aggregate_kernel<<<agg_blocks, 256>>>((const float4*)hin, rowstart, csr,
                                              ahi, alo, N);
        gemm_mma<0><<<gemm_grid, 256, SM_TOTAL>>>(
            nullptr, (const uint4*)ahi, (const uint4*)alo, wa_img,
            ba, nullptr, nullptr, 0.f, z, N, ntiles);
        gemm_mma<1><<<gemm_grid, 256, SM_TOTAL>>>(
            z, nullptr, nullptr, wb_img,
            bb, ga, be, inv_n, hout, N, ntiles);
    };

    layer(x, hA, 0);
    layer(hA, hB, 1);
    layer(hB, hA, 2);

    readout_kernel<<<G, 128>>>(hA, ptr, out);
}

// round 15
// speedup vs baseline: 1.3131x; 1.0869x over previous
#include <cuda_runtime.h>
#include <cuda_fp16.h>
#include <cstdint>

#define HH 128
#define NMAX 50000
#define EMAX 800000
#define BN_EPS 1e-5f
#define APITCH 136
#define WIMG_ELEMS (128 * APITCH)

// ---------------- scratch (no allocations allowed) ----------------
__device__ float g_z[NMAX * HH];
__device__ float g_hA[NMAX * HH];
__device__ float g_hB[NMAX * HH];
__device__ float g_stats[2 * HH];
__device__ int   g_deg[NMAX];
__device__ int   g_slot[EMAX];
__device__ int   g_rowstart[NMAX + 1];
__device__ int   g_csr[EMAX];
__device__ uint2 g_ahi[NMAX * 32];              // agg fp16 plane, row-major
__device__ unsigned short g_w[6][WIMG_ELEMS];   // 6 weight matrices, fp16, [n][k] padded

// ---------------- prep: 6 W fp16 conversions + zero deg/stats ----------
__global__ void prep_kernel(const float* __restrict__ w0, const float* __restrict__ w1,
                            const float* __restrict__ w2, const float* __restrict__ w3,
                            const float* __restrict__ w4, const float* __restrict__ w5,
                            int N) {
    int b = blockIdx.x;
    int tid = threadIdx.x;
    if (b < 384) {
        int wi = b >> 6;
        int i = ((b & 63) << 8) + tid;
        const float* W;
        switch (wi) {
            case 0: W = w0; break;
            case 1: W = w1; break;
            case 2: W = w2; break;
            case 3: W = w3; break;
            case 4: W = w4; break;
            default: W = w5; break;
        }
        int k = i >> 7, n = i & 127;
        float v = __ldg(&W[i]);
        g_w[wi][n * APITCH + k] = __half_as_ushort(__float2half_rn(v));
    } else {
        int idx = (b - 384) * 256 + tid;
        if (idx < N) g_deg[idx] = 0;
        if (b == 384 && tid < 256) g_stats[tid] = 0.f;
    }
}

// ---------------- CSR build ----------------
__global__ void count_kernel(const int* __restrict__ dst, int* __restrict__ deg,
                             int* __restrict__ slot, int E) {
    int e = blockIdx.x * blockDim.x + threadIdx.x;
    if (e < E) slot[e] = atomicAdd(&deg[dst[e]], 1);
}

__global__ void scan_kernel(const int* __restrict__ deg, int* __restrict__ rowstart, int n) {
    __shared__ int warpsum[32];
    __shared__ int s_total;
    __shared__ int s_carry;
    int tid = threadIdx.x, lane = tid & 31, wid = tid >> 5;
    if (tid == 0) s_carry = 0;
    __syncthreads();
    for (int base = 0; base < n; base += 1024) {
        int i = base + tid;
        int v = (i < n) ? deg[i] : 0;
        int incl = v;
#pragma unroll
        for (int off = 1; off < 32; off <<= 1) {
            int t = __shfl_up_sync(0xffffffff, incl, off);
            if (lane >= off) incl += t;
        }
        if (lane == 31) warpsum[wid] = incl;
        __syncthreads();
        if (wid == 0) {
            int w = warpsum[lane];
            int wincl = w;
#pragma unroll
            for (int off = 1; off < 32; off <<= 1) {
                int t = __shfl_up_sync(0xffffffff, wincl, off);
                if (lane >= off) wincl += t;
            }
            warpsum[lane] = wincl - w;
            if (lane == 31) s_total = wincl;
        }
        __syncthreads();
        int carry = s_carry;
        if (i < n) rowstart[i] = carry + warpsum[wid] + incl - v;
        __syncthreads();
        if (tid == 0) s_carry = carry + s_total;
    }
    __syncthreads();
    if (tid == 0) rowstart[n] = s_carry;
}

__global__ void fill_kernel(const int* __restrict__ src, const int* __restrict__ dst,
                            const int* __restrict__ rowstart, const int* __restrict__ slot,
                            int* __restrict__ csr, int E) {
    int e = blockIdx.x * blockDim.x + threadIdx.x;
    if (e >= E) return;
    int d = dst[e];
    csr[__ldg(&rowstart[d]) + slot[e]] = src[e];
}

// ---------------- aggregate -> fp16 plane; block 0 zeroes stats -------
__global__ void aggregate_kernel(const float4* __restrict__ h,
                                 const int* __restrict__ rowstart,
                                 const int* __restrict__ csr,
                                 uint2* __restrict__ ahi, int N) {
    if (blockIdx.x == 0 && threadIdx.x < 256) g_stats[threadIdx.x] = 0.f;
    int warp = (blockIdx.x * blockDim.x + threadIdx.x) >> 5;
    int lane = threadIdx.x & 31;
    if (warp >= N) return;
    int s0 = rowstart[warp], s1 = rowstart[warp + 1];
    float4 acc = __ldg(&h[(size_t)warp * 32 + lane]);
    int j = s0;
    for (; j + 2 <= s1; j += 2) {
        int sa = __ldg(&csr[j]);
        int sb = __ldg(&csr[j + 1]);
        float4 va = __ldg(&h[(size_t)sa * 32 + lane]);
        float4 vb = __ldg(&h[(size_t)sb * 32 + lane]);
        acc.x += va.x + vb.x; acc.y += va.y + vb.y;
        acc.z += va.z + vb.z; acc.w += va.w + vb.w;
    }
    if (j < s1) {
        int sa = __ldg(&csr[j]);
        float4 va = __ldg(&h[(size_t)sa * 32 + lane]);
        acc.x += va.x; acc.y += va.y; acc.z += va.z; acc.w += va.w;
    }
    uint32_t p0 = (uint32_t)__half_as_ushort(__float2half_rn(acc.x)) |
                  ((uint32_t)__half_as_ushort(__float2half_rn(acc.y)) << 16);
    uint32_t p1 = (uint32_t)__half_as_ushort(__float2half_rn(acc.z)) |
                  ((uint32_t)__half_as_ushort(__float2half_rn(acc.w)) << 16);
    ahi[(size_t)warp * 32 + lane] = make_uint2(p0, p1);
}

// ---------------- HMMA GEMM: fp16 single-term, BM=128, 256 thr, persistent ---
#define PLANE_BYTES (128 * APITCH * 2)   // 34816
#define SM_SCALE 0
#define SM_SHIFT 512
#define SM_BIAS  1024
#define SM_AHI   1536
#define SM_BW    (SM_AHI + PLANE_BYTES)
#define SM_TOTAL (SM_BW + PLANE_BYTES)   // 71168

__device__ __forceinline__ void mma16816(float* d, const uint32_t* a, const uint32_t* b) {
    asm volatile(
        "mma.sync.aligned.m16n8k16.row.col.f32.f16.f16.f32 "
        "{%0,%1,%2,%3}, {%4,%5,%6,%7}, {%8,%9}, {%0,%1,%2,%3};"
        : "+f"(d[0]), "+f"(d[1]), "+f"(d[2]), "+f"(d[3])
        : "r"(a[0]), "r"(a[1]), "r"(a[2]), "r"(a[3]), "r"(b[0]), "r"(b[1]));
}

// MODE 0: A from preconverted fp16 plane; out=z; fused BN stats
// MODE 1: A = relu(z*scale+shift) converted to fp16; out = relu(.)
template <int MODE>
__global__ __launch_bounds__(256, 1) void gemm_mma(
    const float* __restrict__ Af32,
    const uint4* __restrict__ Ahi,
    const uint4* __restrict__ Wimg,
    const float* __restrict__ bias, const float* __restrict__ gamma,
    const float* __restrict__ beta, float inv_n,
    float* __restrict__ out, int nrows, int ntiles) {
    extern __shared__ char smem[];
    int tid = threadIdx.x;
    int lane = tid & 31;
    int wid = tid >> 5;
    int groupID = lane >> 2;
    int tig = lane & 3;
    int warp_m = wid & 1;
    int warp_n = wid >> 1;

    float* sh_scale = (float*)(smem + SM_SCALE);
    float* sh_shift = (float*)(smem + SM_SHIFT);
    float* sh_bias  = (float*)(smem + SM_BIAS);

    // ---- once per CTA: bias/scale + W plane ----
    if (tid < 128) {
        sh_bias[tid] = bias[tid];
        if (MODE == 1) {
            float mu = g_stats[tid] * inv_n;
            float var = fmaf(-mu, mu, g_stats[128 + tid] * inv_n);
            float rs = rsqrtf(var + BN_EPS);
            float sc = gamma[tid] * rs;
            sh_scale[tid] = sc;
            sh_shift[tid] = fmaf(-mu, sc, beta[tid]);
        }
    }
    {
        uint4* dw = (uint4*)(smem + SM_BW);
        for (int i = tid; i < PLANE_BYTES / 16; i += 256)
            dw[i] = __ldg(&Wimg[i]);
    }
    if (MODE == 1) __syncthreads();

    for (int tile = blockIdx.x; tile < ntiles; tile += gridDim.x) {
        int block_row = tile * 128;

        // ---- A tile ----
        if (MODE == 0) {
            int r = tid >> 1, half = tid & 1;
            int grow = block_row + r;
            uint32_t dbase = (uint32_t)r * (APITCH * 2) + half * 128;
            const uint4* srch = Ahi + (size_t)grow * 16 + half * 8;
#pragma unroll
            for (int i = 0; i < 8; i++) {
                uint4 vh = (grow < nrows) ? __ldg(&srch[i]) : make_uint4(0, 0, 0, 0);
                *reinterpret_cast<uint4*>(smem + SM_AHI + dbase + i * 16) = vh;
            }
        } else {
            int r = tid >> 1, half = tid & 1;
            int grow = block_row + r;
            const float4* arow =
                reinterpret_cast<const float4*>(Af32 + (size_t)grow * HH + half * 64);
            uint32_t dbase = (uint32_t)r * (APITCH * 2) + half * 128;
#pragma unroll
            for (int i = 0; i < 8; i++) {
                float v[8];
                if (grow < nrows) {
                    float4 p0 = arow[2 * i], p1 = arow[2 * i + 1];
                    v[0] = p0.x; v[1] = p0.y; v[2] = p0.z; v[3] = p0.w;
                    v[4] = p1.x; v[5] = p1.y; v[6] = p1.z; v[7] = p1.w;
                    int c0 = half * 64 + i * 8;
#pragma unroll
                    for (int j = 0; j < 8; j++)
                        v[j] = fmaxf(fmaf(v[j], sh_scale[c0 + j], sh_shift[c0 + j]), 0.f);
                } else {
#pragma unroll
                    for (int j = 0; j < 8; j++) v[j] = 0.f;
                }
                uint32_t hi[4];
#pragma unroll
                for (int j = 0; j < 4; j++)
                    hi[j] = (uint32_t)__half_as_ushort(__float2half_rn(v[2 * j])) |
                            ((uint32_t)__half_as_ushort(__float2half_rn(v[2 * j + 1])) << 16);
                *reinterpret_cast<uint4*>(smem + SM_AHI + dbase + i * 16) =
                    make_uint4(hi[0], hi[1], hi[2], hi[3]);
            }
        }
        __syncthreads();

        // ---- mainloop: 8 k-steps of 16; single term ----
        float acc[4][4][4] = {};
#pragma unroll
        for (int ks = 0; ks < 8; ks++) {
            uint32_t kb = (uint32_t)ks * 32 + tig * 4;
            uint32_t ah[4][4], bw[4][2];
#pragma unroll
            for (int mf = 0; mf < 4; mf++) {
                uint32_t base = (uint32_t)(warp_m * 64 + mf * 16 + groupID) * (APITCH * 2) + kb;
                ah[mf][0] = *(const uint32_t*)(smem + SM_AHI + base);
                ah[mf][1] = *(const uint32_t*)(smem + SM_AHI + base + 8 * APITCH * 2);
                ah[mf][2] = *(const uint32_t*)(smem + SM_AHI + base + 16);
                ah[mf][3] = *(const uint32_t*)(smem + SM_AHI + base + 8 * APITCH * 2 + 16);
            }
#pragma unroll
            for (int nf = 0; nf < 4; nf++) {
                uint32_t base = (uint32_t)(warp_n * 32 + nf * 8 + groupID) * (APITCH * 2) + kb;
                bw[nf][0] = *(const uint32_t*)(smem + SM_BW + base);
                bw[nf][1] = *(const uint32_t*)(smem + SM_BW + base + 16);
            }
#pragma unroll
            for (int mf = 0; mf < 4; mf++)
#pragma unroll
                for (int nf = 0; nf < 4; nf++)
                    mma16816(acc[mf][nf], ah[mf], bw[nf]);
        }

        // ---- epilogue ----
        float cs[4][2] = {}, cq[4][2] = {};
#pragma unroll
        for (int mf = 0; mf < 4; mf++) {
            int r0 = block_row + warp_m * 64 + mf * 16 + groupID;
            int r1 = r0 + 8;
#pragma unroll
            for (int nf = 0; nf < 4; nf++) {
                int c0 = warp_n * 32 + nf * 8 + 2 * tig;
                float b0 = sh_bias[c0], b1 = sh_bias[c0 + 1];
                float t00 = acc[mf][nf][0] + b0, t01 = acc[mf][nf][1] + b1;
                float t10 = acc[mf][nf][2] + b0, t11 = acc[mf][nf][3] + b1;
                if (MODE == 1) {
                    t00 = fmaxf(t00, 0.f); t01 = fmaxf(t01, 0.f);
                    t10 = fmaxf(t10, 0.f); t11 = fmaxf(t11, 0.f);
                }
                if (r0 < nrows) {
                    *reinterpret_cast<float2*>(out + (size_t)r0 * HH + c0) =
                        make_float2(t00, t01);
                    if (MODE == 0) {
                        cs[nf][0] += t00; cq[nf][0] = fmaf(t00, t00, cq[nf][0]);
                        cs[nf][1] += t01; cq[nf][1] = fmaf(t01, t01, cq[nf][1]);
                    }
                }
                if (r1 < nrows) {
                    *reinterpret_cast<float2*>(out + (size_t)r1 * HH + c0) =
                        make_float2(t10, t11);
                    if (MODE == 0) {
                        cs[nf][0] += t10; cq[nf][0] = fmaf(t10, t10, cq[nf][0]);
                        cs[nf][1] += t11; cq[nf][1] = fmaf(t11, t11, cq[nf][1]);
                    }
                }
            }
        }
        if (MODE == 0) {
#pragma unroll
            for (int nf = 0; nf < 4; nf++)
#pragma unroll
                for (int j = 0; j < 2; j++) {
                    float s = cs[nf][j], q = cq[nf][j];
#pragma unroll
                    for (int off = 16; off >= 4; off >>= 1) {
                        s += __shfl_down_sync(0xffffffff, s, off);
                        q += __shfl_down_sync(0xffffffff, q, off);
                    }
                    if (lane < 4) {
                        int col = warp_n * 32 + nf * 8 + 2 * lane + j;
                        atomicAdd(&g_stats[col], s);
                        atomicAdd(&g_stats[128 + col], q);
                    }
                }
        }
        __syncthreads();   // A smem reusable next tile
    }
}

// ---------------- segment-CSR readout ----------------
__global__ void readout_kernel(const float* __restrict__ h,
                               const int* __restrict__ ptr,
                               float* __restrict__ out) {
    int g = blockIdx.x;
    int c = threadIdx.x;
    int s = ptr[g], e = ptr[g + 1];
    float acc = 0.f;
    for (int r = s; r < e; r++) acc += h[r * HH + c];
    out[g * HH + c] = acc;
}

// ---------------- host launch ----------------
extern "C" void kernel_launch(void* const* d_in, const int* in_sizes, int n_in,
                              void* d_out, int out_size) {
    const float* x = (const float*)d_in[0];
    const int* src = (const int*)d_in[1];
    const int* dst = (const int*)d_in[2];
    const int* ptr = (const int*)d_in[3];
    int E = in_sizes[1];
    int N = in_sizes[0] / HH;
    int G = in_sizes[3] - 1;
    float* out = (float*)d_out;

    float *z, *hA, *hB;
    int *deg, *slot, *rowstart, *csr;
    uint2 *ahi;
    unsigned short* wimg;
    cudaGetSymbolAddress((void**)&z, g_z);
    cudaGetSymbolAddress((void**)&hA, g_hA);
    cudaGetSymbolAddress((void**)&hB, g_hB);
    cudaGetSymbolAddress((void**)&deg, g_deg);
    cudaGetSymbolAddress((void**)&slot, g_slot);
    cudaGetSymbolAddress((void**)&rowstart, g_rowstart);
    cudaGetSymbolAddress((void**)&csr, g_csr);
    cudaGetSymbolAddress((void**)&ahi, g_ahi);
    cudaGetSymbolAddress((void**)&wimg, g_w);

    cudaFuncSetAttribute(gemm_mma<0>, cudaFuncAttributeMaxDynamicSharedMemorySize, SM_TOTAL);
    cudaFuncSetAttribute(gemm_mma<1>, cudaFuncAttributeMaxDynamicSharedMemorySize, SM_TOTAL);

    int ntiles = (N + 127) / 128;
    int gemm_grid = ntiles < 148 ? ntiles : 148;
    int eb = (E + 255) / 256;
    int agg_blocks = (int)(((long long)N * 32 + 255) / 256);
    float inv_n = 1.0f / (float)N;

    int zero_blocks = (N + 255) / 256;
    prep_kernel<<<384 + zero_blocks, 256>>>(
        (const float*)d_in[4], (const float*)d_in[8],
        (const float*)d_in[10], (const float*)d_in[14],
        (const float*)d_in[16], (const float*)d_in[20], N);
    count_kernel<<<eb, 256>>>(dst, deg, slot, E);
    scan_kernel<<<1, 1024>>>(deg, rowstart, N);
    fill_kernel<<<eb, 256>>>(src, dst, rowstart, slot, csr, E);

    auto layer = [&](const float* hin, float* hout, int li) {
        int base = 4 + 6 * li;
        const float* ba = (const float*)d_in[base + 1];
        const float* ga = (const float*)d_in[base + 2];
        const float* be = (const float*)d_in[base + 3];
        const float* bb = (const float*)d_in[base + 5];
        const uint4* wa_img = (const uint4*)(wimg + (size_t)(2 * li + 0) * WIMG_ELEMS);
        const uint4* wb_img = (const uint4*)(wimg + (size_t)(2 * li + 1) * WIMG_ELEMS);

        aggregate_kernel<<<agg_blocks, 256>>>((const float4*)hin, rowstart, csr,
                                              ahi, N);
        gemm_mma<0><<<gemm_grid, 256, SM_TOTAL>>>(
            nullptr, (const uint4*)ahi, wa_img,
            ba, nullptr, nullptr, 0.f, z, N, ntiles);
        gemm_mma<1><<<gemm_grid, 256, SM_TOTAL>>>(
            z, nullptr, wb_img,
            bb, ga, be, inv_n, hout, N, ntiles);
    };

    layer(x, hA, 0);
    layer(hA, hB, 1);
    layer(hB, hA, 2);

    readout_kernel<<<G, 128>>>(hA, ptr, out);
}

// round 16
// speedup vs baseline: 1.3420x; 1.0220x over previous
#include <cuda_runtime.h>
#include <cuda_fp16.h>
#include <cstdint>

#define HH 128
#define NMAX 50000
#define EMAX 800000
#define BN_EPS 1e-5f
#define APITCH 136
#define WIMG_ELEMS (128 * APITCH)

// ---------------- scratch (no allocations allowed) ----------------
__device__ float g_z[NMAX * HH];
__device__ unsigned short g_hA[NMAX * HH];      // fp16 hidden states
__device__ unsigned short g_hB[NMAX * HH];
__device__ float g_stats[2 * HH];
__device__ int   g_deg[NMAX];
__device__ int   g_slot[EMAX];
__device__ int   g_rowstart[NMAX + 1];
__device__ int   g_csr[EMAX];
__device__ uint2 g_ahi[NMAX * 32];              // agg fp16 plane, row-major
__device__ unsigned short g_w[6][WIMG_ELEMS];   // 6 weight matrices, fp16, [n][k] padded

// ---------------- prep: 6 W fp16 conversions + zero deg/stats ----------
__global__ void prep_kernel(const float* __restrict__ w0, const float* __restrict__ w1,
                            const float* __restrict__ w2, const float* __restrict__ w3,
                            const float* __restrict__ w4, const float* __restrict__ w5,
                            int N) {
    int b = blockIdx.x;
    int tid = threadIdx.x;
    if (b < 384) {
        int wi = b >> 6;
        int i = ((b & 63) << 8) + tid;
        const float* W;
        switch (wi) {
            case 0: W = w0; break;
            case 1: W = w1; break;
            case 2: W = w2; break;
            case 3: W = w3; break;
            case 4: W = w4; break;
            default: W = w5; break;
        }
        int k = i >> 7, n = i & 127;
        float v = __ldg(&W[i]);
        g_w[wi][n * APITCH + k] = __half_as_ushort(__float2half_rn(v));
    } else {
        int idx = (b - 384) * 256 + tid;
        if (idx < N) g_deg[idx] = 0;
        if (b == 384 && tid < 256) g_stats[tid] = 0.f;
    }
}

// ---------------- CSR build ----------------
__global__ void count_kernel(const int* __restrict__ dst, int* __restrict__ deg,
                             int* __restrict__ slot, int E) {
    int e = blockIdx.x * blockDim.x + threadIdx.x;
    if (e < E) slot[e] = atomicAdd(&deg[dst[e]], 1);
}

__global__ void scan_kernel(const int* __restrict__ deg, int* __restrict__ rowstart, int n) {
    __shared__ int warpsum[32];
    __shared__ int s_total;
    __shared__ int s_carry;
    int tid = threadIdx.x, lane = tid & 31, wid = tid >> 5;
    if (tid == 0) s_carry = 0;
    __syncthreads();
    for (int base = 0; base < n; base += 1024) {
        int i = base + tid;
        int v = (i < n) ? deg[i] : 0;
        int incl = v;
#pragma unroll
        for (int off = 1; off < 32; off <<= 1) {
            int t = __shfl_up_sync(0xffffffff, incl, off);
            if (lane >= off) incl += t;
        }
        if (lane == 31) warpsum[wid] = incl;
        __syncthreads();
        if (wid == 0) {
            int w = warpsum[lane];
            int wincl = w;
#pragma unroll
            for (int off = 1; off < 32; off <<= 1) {
                int t = __shfl_up_sync(0xffffffff, wincl, off);
                if (lane >= off) wincl += t;
            }
            warpsum[lane] = wincl - w;
            if (lane == 31) s_total = wincl;
        }
        __syncthreads();
        int carry = s_carry;
        if (i < n) rowstart[i] = carry + warpsum[wid] + incl - v;
        __syncthreads();
        if (tid == 0) s_carry = carry + s_total;
    }
    __syncthreads();
    if (tid == 0) rowstart[n] = s_carry;
}

__global__ void fill_kernel(const int* __restrict__ src, const int* __restrict__ dst,
                            const int* __restrict__ rowstart, const int* __restrict__ slot,
                            int* __restrict__ csr, int E) {
    int e = blockIdx.x * blockDim.x + threadIdx.x;
    if (e >= E) return;
    int d = dst[e];
    csr[__ldg(&rowstart[d]) + slot[e]] = src[e];
}

// ---------------- aggregate (fp32 input, layer 1) -> fp16 plane --------------
__global__ void aggregate_f32_kernel(const float4* __restrict__ h,
                                     const int* __restrict__ rowstart,
                                     const int* __restrict__ csr,
                                     uint2* __restrict__ ahi, int N) {
    if (blockIdx.x == 0 && threadIdx.x < 256) g_stats[threadIdx.x] = 0.f;
    int warp = (blockIdx.x * blockDim.x + threadIdx.x) >> 5;
    int lane = threadIdx.x & 31;
    if (warp >= N) return;
    int s0 = rowstart[warp], s1 = rowstart[warp + 1];
    float4 acc = __ldg(&h[(size_t)warp * 32 + lane]);
    int j = s0;
    for (; j + 2 <= s1; j += 2) {
        int sa = __ldg(&csr[j]);
        int sb = __ldg(&csr[j + 1]);
        float4 va = __ldg(&h[(size_t)sa * 32 + lane]);
        float4 vb = __ldg(&h[(size_t)sb * 32 + lane]);
        acc.x += va.x + vb.x; acc.y += va.y + vb.y;
        acc.z += va.z + vb.z; acc.w += va.w + vb.w;
    }
    if (j < s1) {
        int sa = __ldg(&csr[j]);
        float4 va = __ldg(&h[(size_t)sa * 32 + lane]);
        acc.x += va.x; acc.y += va.y; acc.z += va.z; acc.w += va.w;
    }
    uint32_t p0 = (uint32_t)__half_as_ushort(__float2half_rn(acc.x)) |
                  ((uint32_t)__half_as_ushort(__float2half_rn(acc.y)) << 16);
    uint32_t p1 = (uint32_t)__half_as_ushort(__float2half_rn(acc.z)) |
                  ((uint32_t)__half_as_ushort(__float2half_rn(acc.w)) << 16);
    ahi[(size_t)warp * 32 + lane] = make_uint2(p0, p1);
}

// ---------------- aggregate (fp16 input, layers 2-3) -> fp16 plane -----------
// lane handles 4 halves (uint2 = 8 bytes); gather traffic halves vs fp32
__global__ void aggregate_f16_kernel(const uint2* __restrict__ h,
                                     const int* __restrict__ rowstart,
                                     const int* __restrict__ csr,
                                     uint2* __restrict__ ahi, int N) {
    if (blockIdx.x == 0 && threadIdx.x < 256) g_stats[threadIdx.x] = 0.f;
    int warp = (blockIdx.x * blockDim.x + threadIdx.x) >> 5;
    int lane = threadIdx.x & 31;
    if (warp >= N) return;
    int s0 = rowstart[warp], s1 = rowstart[warp + 1];
    uint2 self = __ldg(&h[(size_t)warp * 32 + lane]);
    float2 a0 = __half22float2(*reinterpret_cast<__half2*>(&self.x));
    float2 a1 = __half22float2(*reinterpret_cast<__half2*>(&self.y));
    float4 acc = make_float4(a0.x, a0.y, a1.x, a1.y);
    int j = s0;
    for (; j + 2 <= s1; j += 2) {
        int sa = __ldg(&csr[j]);
        int sb = __ldg(&csr[j + 1]);
        uint2 va = __ldg(&h[(size_t)sa * 32 + lane]);
        uint2 vb = __ldg(&h[(size_t)sb * 32 + lane]);
        float2 va0 = __half22float2(*reinterpret_cast<__half2*>(&va.x));
        float2 va1 = __half22float2(*reinterpret_cast<__half2*>(&va.y));
        float2 vb0 = __half22float2(*reinterpret_cast<__half2*>(&vb.x));
        float2 vb1 = __half22float2(*reinterpret_cast<__half2*>(&vb.y));
        acc.x += va0.x + vb0.x; acc.y += va0.y + vb0.y;
        acc.z += va1.x + vb1.x; acc.w += va1.y + vb1.y;
    }
    if (j < s1) {
        int sa = __ldg(&csr[j]);
        uint2 va = __ldg(&h[(size_t)sa * 32 + lane]);
        float2 va0 = __half22float2(*reinterpret_cast<__half2*>(&va.x));
        float2 va1 = __half22float2(*reinterpret_cast<__half2*>(&va.y));
        acc.x += va0.x; acc.y += va0.y; acc.z += va1.x; acc.w += va1.y;
    }
    uint32_t p0 = (uint32_t)__half_as_ushort(__float2half_rn(acc.x)) |
                  ((uint32_t)__half_as_ushort(__float2half_rn(acc.y)) << 16);
    uint32_t p1 = (uint32_t)__half_as_ushort(__float2half_rn(acc.z)) |
                  ((uint32_t)__half_as_ushort(__float2half_rn(acc.w)) << 16);
    ahi[(size_t)warp * 32 + lane] = make_uint2(p0, p1);
}

// ---------------- HMMA GEMM: fp16 single-term, BM=128, 256 thr, persistent ---
#define PLANE_BYTES (128 * APITCH * 2)   // 34816
#define SM_SCALE 0
#define SM_SHIFT 512
#define SM_BIAS  1024
#define SM_AHI   1536
#define SM_BW    (SM_AHI + PLANE_BYTES)
#define SM_TOTAL (SM_BW + PLANE_BYTES)   // 71168

__device__ __forceinline__ void mma16816(float* d, const uint32_t* a, const uint32_t* b) {
    asm volatile(
        "mma.sync.aligned.m16n8k16.row.col.f32.f16.f16.f32 "
        "{%0,%1,%2,%3}, {%4,%5,%6,%7}, {%8,%9}, {%0,%1,%2,%3};"
        : "+f"(d[0]), "+f"(d[1]), "+f"(d[2]), "+f"(d[3])
        : "r"(a[0]), "r"(a[1]), "r"(a[2]), "r"(a[3]), "r"(b[0]), "r"(b[1]));
}

// MODE 0: A from preconverted fp16 plane; out=z (fp32); fused BN stats
// MODE 1: A = relu(z*scale+shift) fp16; out = relu(.) stored as fp16
template <int MODE>
__global__ __launch_bounds__(256, 1) void gemm_mma(
    const float* __restrict__ Af32,
    const uint4* __restrict__ Ahi,
    const uint4* __restrict__ Wimg,
    const float* __restrict__ bias, const float* __restrict__ gamma,
    const float* __restrict__ beta, float inv_n,
    void* __restrict__ out_v, int nrows, int ntiles) {
    extern __shared__ char smem[];
    int tid = threadIdx.x;
    int lane = tid & 31;
    int wid = tid >> 5;
    int groupID = lane >> 2;
    int tig = lane & 3;
    int warp_m = wid & 1;
    int warp_n = wid >> 1;

    float* sh_scale = (float*)(smem + SM_SCALE);
    float* sh_shift = (float*)(smem + SM_SHIFT);
    float* sh_bias  = (float*)(smem + SM_BIAS);

    // ---- once per CTA: bias/scale + W plane ----
    if (tid < 128) {
        sh_bias[tid] = bias[tid];
        if (MODE == 1) {
            float mu = g_stats[tid] * inv_n;
            float var = fmaf(-mu, mu, g_stats[128 + tid] * inv_n);
            float rs = rsqrtf(var + BN_EPS);
            float sc = gamma[tid] * rs;
            sh_scale[tid] = sc;
            sh_shift[tid] = fmaf(-mu, sc, beta[tid]);
        }
    }
    {
        uint4* dw = (uint4*)(smem + SM_BW);
        for (int i = tid; i < PLANE_BYTES / 16; i += 256)
            dw[i] = __ldg(&Wimg[i]);
    }
    if (MODE == 1) __syncthreads();

    for (int tile = blockIdx.x; tile < ntiles; tile += gridDim.x) {
        int block_row = tile * 128;

        // ---- A tile ----
        if (MODE == 0) {
            int r = tid >> 1, half = tid & 1;
            int grow = block_row + r;
            uint32_t dbase = (uint32_t)r * (APITCH * 2) + half * 128;
            const uint4* srch = Ahi + (size_t)grow * 16 + half * 8;
#pragma unroll
            for (int i = 0; i < 8; i++) {
                uint4 vh = (grow < nrows) ? __ldg(&srch[i]) : make_uint4(0, 0, 0, 0);
                *reinterpret_cast<uint4*>(smem + SM_AHI + dbase + i * 16) = vh;
            }
        } else {
            int r = tid >> 1, half = tid & 1;
            int grow = block_row + r;
            const float4* arow =
                reinterpret_cast<const float4*>(Af32 + (size_t)grow * HH + half * 64);
            uint32_t dbase = (uint32_t)r * (APITCH * 2) + half * 128;
#pragma unroll
            for (int i = 0; i < 8; i++) {
                float v[8];
                if (grow < nrows) {
                    float4 p0 = arow[2 * i], p1 = arow[2 * i + 1];
                    v[0] = p0.x; v[1] = p0.y; v[2] = p0.z; v[3] = p0.w;
                    v[4] = p1.x; v[5] = p1.y; v[6] = p1.z; v[7] = p1.w;
                    int c0 = half * 64 + i * 8;
#pragma unroll
                    for (int j = 0; j < 8; j++)
                        v[j] = fmaxf(fmaf(v[j], sh_scale[c0 + j], sh_shift[c0 + j]), 0.f);
                } else {
#pragma unroll
                    for (int j = 0; j < 8; j++) v[j] = 0.f;
                }
                uint32_t hi[4];
#pragma unroll
                for (int j = 0; j < 4; j++)
                    hi[j] = (uint32_t)__half_as_ushort(__float2half_rn(v[2 * j])) |
                            ((uint32_t)__half_as_ushort(__float2half_rn(v[2 * j + 1])) << 16);
                *reinterpret_cast<uint4*>(smem + SM_AHI + dbase + i * 16) =
                    make_uint4(hi[0], hi[1], hi[2], hi[3]);
            }
        }
        __syncthreads();

        // ---- mainloop: 8 k-steps of 16; single term ----
        float acc[4][4][4] = {};
#pragma unroll
        for (int ks = 0; ks < 8; ks++) {
            uint32_t kb = (uint32_t)ks * 32 + tig * 4;
            uint32_t ah[4][4], bw[4][2];
#pragma unroll
            for (int mf = 0; mf < 4; mf++) {
                uint32_t base = (uint32_t)(warp_m * 64 + mf * 16 + groupID) * (APITCH * 2) + kb;
                ah[mf][0] = *(const uint32_t*)(smem + SM_AHI + base);
                ah[mf][1] = *(const uint32_t*)(smem + SM_AHI + base + 8 * APITCH * 2);
                ah[mf][2] = *(const uint32_t*)(smem + SM_AHI + base + 16);
                ah[mf][3] = *(const uint32_t*)(smem + SM_AHI + base + 8 * APITCH * 2 + 16);
            }
#pragma unroll
            for (int nf = 0; nf < 4; nf++) {
                uint32_t base = (uint32_t)(warp_n * 32 + nf * 8 + groupID) * (APITCH * 2) + kb;
                bw[nf][0] = *(const uint32_t*)(smem + SM_BW + base);
                bw[nf][1] = *(const uint32_t*)(smem + SM_BW + base + 16);
            }
#pragma unroll
            for (int mf = 0; mf < 4; mf++)
#pragma unroll
                for (int nf = 0; nf < 4; nf++)
                    mma16816(acc[mf][nf], ah[mf], bw[nf]);
        }

        // ---- epilogue ----
        float* outf = (float*)out_v;
        __half* outh = (__half*)out_v;
        float cs[4][2] = {}, cq[4][2] = {};
#pragma unroll
        for (int mf = 0; mf < 4; mf++) {
            int r0 = block_row + warp_m * 64 + mf * 16 + groupID;
            int r1 = r0 + 8;
#pragma unroll
            for (int nf = 0; nf < 4; nf++) {
                int c0 = warp_n * 32 + nf * 8 + 2 * tig;
                float b0 = sh_bias[c0], b1 = sh_bias[c0 + 1];
                float t00 = acc[mf][nf][0] + b0, t01 = acc[mf][nf][1] + b1;
                float t10 = acc[mf][nf][2] + b0, t11 = acc[mf][nf][3] + b1;
                if (MODE == 1) {
                    t00 = fmaxf(t00, 0.f); t01 = fmaxf(t01, 0.f);
                    t10 = fmaxf(t10, 0.f); t11 = fmaxf(t11, 0.f);
                }
                if (r0 < nrows) {
                    if (MODE == 0) {
                        *reinterpret_cast<float2*>(outf + (size_t)r0 * HH + c0) =
                            make_float2(t00, t01);
                        cs[nf][0] += t00; cq[nf][0] = fmaf(t00, t00, cq[nf][0]);
                        cs[nf][1] += t01; cq[nf][1] = fmaf(t01, t01, cq[nf][1]);
                    } else {
                        *reinterpret_cast<__half2*>(outh + (size_t)r0 * HH + c0) =
                            __floats2half2_rn(t00, t01);
                    }
                }
                if (r1 < nrows) {
                    if (MODE == 0) {
                        *reinterpret_cast<float2*>(outf + (size_t)r1 * HH + c0) =
                            make_float2(t10, t11);
                        cs[nf][0] += t10; cq[nf][0] = fmaf(t10, t10, cq[nf][0]);
                        cs[nf][1] += t11; cq[nf][1] = fmaf(t11, t11, cq[nf][1]);
                    } else {
                        *reinterpret_cast<__half2*>(outh + (size_t)r1 * HH + c0) =
                            __floats2half2_rn(t10, t11);
                    }
                }
            }
        }
        if (MODE == 0) {
#pragma unroll
            for (int nf = 0; nf < 4; nf++)
#pragma unroll
                for (int j = 0; j < 2; j++) {
                    float s = cs[nf][j], q = cq[nf][j];
#pragma unroll
                    for (int off = 16; off >= 4; off >>= 1) {
                        s += __shfl_down_sync(0xffffffff, s, off);
                        q += __shfl_down_sync(0xffffffff, q, off);
                    }
                    if (lane < 4) {
                        int col = warp_n * 32 + nf * 8 + 2 * lane + j;
                        atomicAdd(&g_stats[col], s);
                        atomicAdd(&g_stats[128 + col], q);
                    }
                }
        }
        __syncthreads();   // A smem reusable next tile
    }
}

// ---------------- segment-CSR readout (fp16 h) ----------------
__global__ void readout_kernel(const __half* __restrict__ h,
                               const int* __restrict__ ptr,
                               float* __restrict__ out) {
    int g = blockIdx.x;
    int c = threadIdx.x;
    int s = ptr[g], e = ptr[g + 1];
    float acc = 0.f;
    for (int r = s; r < e; r++) acc += __half2float(h[(size_t)r * HH + c]);
    out[g * HH + c] = acc;
}

// ---------------- host launch ----------------
extern "C" void kernel_launch(void* const* d_in, const int* in_sizes, int n_in,
                              void* d_out, int out_size) {
    const float* x = (const float*)d_in[0];
    const int* src = (const int*)d_in[1];
    const int* dst = (const int*)d_in[2];
    const int* ptr = (const int*)d_in[3];
    int E = in_sizes[1];
    int N = in_sizes[0] / HH;
    int G = in_sizes[3] - 1;
    float* out = (float*)d_out;

    float* z;
    unsigned short *hA, *hB;
    int *deg, *slot, *rowstart, *csr;
    uint2* ahi;
    unsigned short* wimg;
    cudaGetSymbolAddress((void**)&z, g_z);
    cudaGetSymbolAddress((void**)&hA, g_hA);
    cudaGetSymbolAddress((void**)&hB, g_hB);
    cudaGetSymbolAddress((void**)&deg, g_deg);
    cudaGetSymbolAddress((void**)&slot, g_slot);
    cudaGetSymbolAddress((void**)&rowstart, g_rowstart);
    cudaGetSymbolAddress((void**)&csr, g_csr);
    cudaGetSymbolAddress((void**)&ahi, g_ahi);
    cudaGetSymbolAddress((void**)&wimg, g_w);

    cudaFuncSetAttribute(gemm_mma<0>, cudaFuncAttributeMaxDynamicSharedMemorySize, SM_TOTAL);
    cudaFuncSetAttribute(gemm_mma<1>, cudaFuncAttributeMaxDynamicSharedMemorySize, SM_TOTAL);

    int ntiles = (N + 127) / 128;
    int gemm_grid = ntiles < 148 ? ntiles : 148;
    int eb = (E + 255) / 256;
    int agg_blocks = (int)(((long long)N * 32 + 255) / 256);
    float inv_n = 1.0f / (float)N;

    int zero_blocks = (N + 255) / 256;
    prep_kernel<<<384 + zero_blocks, 256>>>(
        (const float*)d_in[4], (const float*)d_in[8],
        (const float*)d_in[10], (const float*)d_in[14],
        (const float*)d_in[16], (const float*)d_in[20], N);
    count_kernel<<<eb, 256>>>(dst, deg, slot, E);
    scan_kernel<<<1, 1024>>>(deg, rowstart, N);
    fill_kernel<<<eb, 256>>>(src, dst, rowstart, slot, csr, E);

    auto layer = [&](const void* hin, bool hin_f16, void* hout, int li) {
        int base = 4 + 6 * li;
        const float* ba = (const float*)d_in[base + 1];
        const float* ga = (const float*)d_in[base + 2];
        const float* be = (const float*)d_in[base + 3];
        const float* bb = (const float*)d_in[base + 5];
        const uint4* wa_img = (const uint4*)(wimg + (size_t)(2 * li + 0) * WIMG_ELEMS);
        const uint4* wb_img = (const uint4*)(wimg + (size_t)(2 * li + 1) * WIMG_ELEMS);

        if (hin_f16)
            aggregate_f16_kernel<<<agg_blocks, 256>>>((const uint2*)hin, rowstart,
                                                      csr, ahi, N);
        else
            aggregate_f32_kernel<<<agg_blocks, 256>>>((const float4*)hin, rowstart,
                                                      csr, ahi, N);
        gemm_mma<0><<<gemm_grid, 256, SM_TOTAL>>>(
            nullptr, (const uint4*)ahi, wa_img,
            ba, nullptr, nullptr, 0.f, z, N, ntiles);
        gemm_mma<1><<<gemm_grid, 256, SM_TOTAL>>>(
            z, nullptr, wb_img,
            bb, ga, be, inv_n, hout, N, ntiles);
    };

    layer(x, false, hA, 0);
    layer(hA, true, hB, 1);
    layer(hB, true, hA, 2);

    readout_kernel<<<G, 128>>>((const __half*)hA, ptr, out);
}

// round 17
// speedup vs baseline: 1.3545x; 1.0093x over previous
#include <cuda_runtime.h>
#include <cuda_fp16.h>
#include <cstdint>

#define HH 128
#define NMAX 50000
#define EMAX 800000
#define BN_EPS 1e-5f
#define APITCH 136
#define WIMG_ELEMS (128 * APITCH)

// ---------------- scratch (no allocations allowed) ----------------
__device__ unsigned short g_z[NMAX * HH];       // fp16 pre-BN activations
__device__ unsigned short g_hA[NMAX * HH];      // fp16 hidden states
__device__ unsigned short g_hB[NMAX * HH];
__device__ float g_stats[2 * HH];
__device__ int   g_deg[NMAX];
__device__ int   g_slot[EMAX];
__device__ int   g_rowstart[NMAX + 1];
__device__ int   g_csr[EMAX];
__device__ uint2 g_ahi[NMAX * 32];              // agg fp16 plane, row-major
__device__ unsigned short g_w[6][WIMG_ELEMS];   // 6 weight matrices, fp16, [n][k] padded

// ---------------- prep: 6 W fp16 conversions + zero deg/stats ----------
__global__ void prep_kernel(const float* __restrict__ w0, const float* __restrict__ w1,
                            const float* __restrict__ w2, const float* __restrict__ w3,
                            const float* __restrict__ w4, const float* __restrict__ w5,
                            int N) {
    int b = blockIdx.x;
    int tid = threadIdx.x;
    if (b < 384) {
        int wi = b >> 6;
        int i = ((b & 63) << 8) + tid;
        const float* W;
        switch (wi) {
            case 0: W = w0; break;
            case 1: W = w1; break;
            case 2: W = w2; break;
            case 3: W = w3; break;
            case 4: W = w4; break;
            default: W = w5; break;
        }
        int k = i >> 7, n = i & 127;
        float v = __ldg(&W[i]);
        g_w[wi][n * APITCH + k] = __half_as_ushort(__float2half_rn(v));
    } else {
        int idx = (b - 384) * 256 + tid;
        if (idx < N) g_deg[idx] = 0;
        if (b == 384 && tid < 256) g_stats[tid] = 0.f;
    }
}

// ---------------- CSR build ----------------
__global__ void count_kernel(const int* __restrict__ dst, int* __restrict__ deg,
                             int* __restrict__ slot, int E) {
    int e = blockIdx.x * blockDim.x + threadIdx.x;
    if (e < E) slot[e] = atomicAdd(&deg[dst[e]], 1);
}

__global__ void scan_kernel(const int* __restrict__ deg, int* __restrict__ rowstart, int n) {
    __shared__ int warpsum[32];
    __shared__ int s_total;
    __shared__ int s_carry;
    int tid = threadIdx.x, lane = tid & 31, wid = tid >> 5;
    if (tid == 0) s_carry = 0;
    __syncthreads();
    for (int base = 0; base < n; base += 1024) {
        int i = base + tid;
        int v = (i < n) ? deg[i] : 0;
        int incl = v;
#pragma unroll
        for (int off = 1; off < 32; off <<= 1) {
            int t = __shfl_up_sync(0xffffffff, incl, off);
            if (lane >= off) incl += t;
        }
        if (lane == 31) warpsum[wid] = incl;
        __syncthreads();
        if (wid == 0) {
            int w = warpsum[lane];
            int wincl = w;
#pragma unroll
            for (int off = 1; off < 32; off <<= 1) {
                int t = __shfl_up_sync(0xffffffff, wincl, off);
                if (lane >= off) wincl += t;
            }
            warpsum[lane] = wincl - w;
            if (lane == 31) s_total = wincl;
        }
        __syncthreads();
        int carry = s_carry;
        if (i < n) rowstart[i] = carry + warpsum[wid] + incl - v;
        __syncthreads();
        if (tid == 0) s_carry = carry + s_total;
    }
    __syncthreads();
    if (tid == 0) rowstart[n] = s_carry;
}

__global__ void fill_kernel(const int* __restrict__ src, const int* __restrict__ dst,
                            const int* __restrict__ rowstart, const int* __restrict__ slot,
                            int* __restrict__ csr, int E) {
    int e = blockIdx.x * blockDim.x + threadIdx.x;
    if (e >= E) return;
    int d = dst[e];
    csr[__ldg(&rowstart[d]) + slot[e]] = src[e];
}

// ---------------- aggregate (fp32 input, layer 1) -> fp16 plane; unroll 4 ----
__global__ void aggregate_f32_kernel(const float4* __restrict__ h,
                                     const int* __restrict__ rowstart,
                                     const int* __restrict__ csr,
                                     uint2* __restrict__ ahi, int N) {
    if (blockIdx.x == 0 && threadIdx.x < 256) g_stats[threadIdx.x] = 0.f;
    int warp = (blockIdx.x * blockDim.x + threadIdx.x) >> 5;
    int lane = threadIdx.x & 31;
    if (warp >= N) return;
    int s0 = rowstart[warp], s1 = rowstart[warp + 1];
    float4 acc = __ldg(&h[(size_t)warp * 32 + lane]);
    int j = s0;
    for (; j + 4 <= s1; j += 4) {
        int sa = __ldg(&csr[j]);
        int sb = __ldg(&csr[j + 1]);
        int sc = __ldg(&csr[j + 2]);
        int sd = __ldg(&csr[j + 3]);
        float4 va = __ldg(&h[(size_t)sa * 32 + lane]);
        float4 vb = __ldg(&h[(size_t)sb * 32 + lane]);
        float4 vc = __ldg(&h[(size_t)sc * 32 + lane]);
        float4 vd = __ldg(&h[(size_t)sd * 32 + lane]);
        acc.x += (va.x + vb.x) + (vc.x + vd.x);
        acc.y += (va.y + vb.y) + (vc.y + vd.y);
        acc.z += (va.z + vb.z) + (vc.z + vd.z);
        acc.w += (va.w + vb.w) + (vc.w + vd.w);
    }
    for (; j < s1; j++) {
        int sa = __ldg(&csr[j]);
        float4 va = __ldg(&h[(size_t)sa * 32 + lane]);
        acc.x += va.x; acc.y += va.y; acc.z += va.z; acc.w += va.w;
    }
    uint32_t p0 = (uint32_t)__half_as_ushort(__float2half_rn(acc.x)) |
                  ((uint32_t)__half_as_ushort(__float2half_rn(acc.y)) << 16);
    uint32_t p1 = (uint32_t)__half_as_ushort(__float2half_rn(acc.z)) |
                  ((uint32_t)__half_as_ushort(__float2half_rn(acc.w)) << 16);
    ahi[(size_t)warp * 32 + lane] = make_uint2(p0, p1);
}

// ---------------- aggregate (fp16 input, layers 2-3); unroll 4 ---------------
__global__ void aggregate_f16_kernel(const uint2* __restrict__ h,
                                     const int* __restrict__ rowstart,
                                     const int* __restrict__ csr,
                                     uint2* __restrict__ ahi, int N) {
    if (blockIdx.x == 0 && threadIdx.x < 256) g_stats[threadIdx.x] = 0.f;
    int warp = (blockIdx.x * blockDim.x + threadIdx.x) >> 5;
    int lane = threadIdx.x & 31;
    if (warp >= N) return;
    int s0 = rowstart[warp], s1 = rowstart[warp + 1];
    uint2 self = __ldg(&h[(size_t)warp * 32 + lane]);
    float2 a0 = __half22float2(*reinterpret_cast<__half2*>(&self.x));
    float2 a1 = __half22float2(*reinterpret_cast<__half2*>(&self.y));
    float4 acc = make_float4(a0.x, a0.y, a1.x, a1.y);
    int j = s0;
    for (; j + 4 <= s1; j += 4) {
        int sa = __ldg(&csr[j]);
        int sb = __ldg(&csr[j + 1]);
        int sc = __ldg(&csr[j + 2]);
        int sd = __ldg(&csr[j + 3]);
        uint2 va = __ldg(&h[(size_t)sa * 32 + lane]);
        uint2 vb = __ldg(&h[(size_t)sb * 32 + lane]);
        uint2 vc = __ldg(&h[(size_t)sc * 32 + lane]);
        uint2 vd = __ldg(&h[(size_t)sd * 32 + lane]);
        float2 fa0 = __half22float2(*reinterpret_cast<__half2*>(&va.x));
        float2 fa1 = __half22float2(*reinterpret_cast<__half2*>(&va.y));
        float2 fb0 = __half22float2(*reinterpret_cast<__half2*>(&vb.x));
        float2 fb1 = __half22float2(*reinterpret_cast<__half2*>(&vb.y));
        float2 fc0 = __half22float2(*reinterpret_cast<__half2*>(&vc.x));
        float2 fc1 = __half22float2(*reinterpret_cast<__half2*>(&vc.y));
        float2 fd0 = __half22float2(*reinterpret_cast<__half2*>(&vd.x));
        float2 fd1 = __half22float2(*reinterpret_cast<__half2*>(&vd.y));
        acc.x += (fa0.x + fb0.x) + (fc0.x + fd0.x);
        acc.y += (fa0.y + fb0.y) + (fc0.y + fd0.y);
        acc.z += (fa1.x + fb1.x) + (fc1.x + fd1.x);
        acc.w += (fa1.y + fb1.y) + (fc1.y + fd1.y);
    }
    for (; j < s1; j++) {
        int sa = __ldg(&csr[j]);
        uint2 va = __ldg(&h[(size_t)sa * 32 + lane]);
        float2 fa0 = __half22float2(*reinterpret_cast<__half2*>(&va.x));
        float2 fa1 = __half22float2(*reinterpret_cast<__half2*>(&va.y));
        acc.x += fa0.x; acc.y += fa0.y; acc.z += fa1.x; acc.w += fa1.y;
    }
    uint32_t p0 = (uint32_t)__half_as_ushort(__float2half_rn(acc.x)) |
                  ((uint32_t)__half_as_ushort(__float2half_rn(acc.y)) << 16);
    uint32_t p1 = (uint32_t)__half_as_ushort(__float2half_rn(acc.z)) |
                  ((uint32_t)__half_as_ushort(__float2half_rn(acc.w)) << 16);
    ahi[(size_t)warp * 32 + lane] = make_uint2(p0, p1);
}

// ---------------- HMMA GEMM: fp16 single-term, BM=128, 256 thr, persistent ---
#define PLANE_BYTES (128 * APITCH * 2)   // 34816
#define SM_SCALE 0
#define SM_SHIFT 512
#define SM_BIAS  1024
#define SM_AHI   1536
#define SM_BW    (SM_AHI + PLANE_BYTES)
#define SM_TOTAL (SM_BW + PLANE_BYTES)   // 71168

__device__ __forceinline__ void mma16816(float* d, const uint32_t* a, const uint32_t* b) {
    asm volatile(
        "mma.sync.aligned.m16n8k16.row.col.f32.f16.f16.f32 "
        "{%0,%1,%2,%3}, {%4,%5,%6,%7}, {%8,%9}, {%0,%1,%2,%3};"
        : "+f"(d[0]), "+f"(d[1]), "+f"(d[2]), "+f"(d[3])
        : "r"(a[0]), "r"(a[1]), "r"(a[2]), "r"(a[3]), "r"(b[0]), "r"(b[1]));
}

// MODE 0: A from preconverted fp16 plane (Ahi); out = z fp16; fused BN stats
// MODE 1: A = relu(z*scale+shift) from fp16 z (Azh); out = h fp16
template <int MODE>
__global__ __launch_bounds__(256, 1) void gemm_mma(
    const uint4* __restrict__ Azh,
    const uint4* __restrict__ Ahi,
    const uint4* __restrict__ Wimg,
    const float* __restrict__ bias, const float* __restrict__ gamma,
    const float* __restrict__ beta, float inv_n,
    __half* __restrict__ out, int nrows, int ntiles) {
    extern __shared__ char smem[];
    int tid = threadIdx.x;
    int lane = tid & 31;
    int wid = tid >> 5;
    int groupID = lane >> 2;
    int tig = lane & 3;
    int warp_m = wid & 1;
    int warp_n = wid >> 1;

    float* sh_scale = (float*)(smem + SM_SCALE);
    float* sh_shift = (float*)(smem + SM_SHIFT);
    float* sh_bias  = (float*)(smem + SM_BIAS);

    // ---- once per CTA: bias/scale + W plane ----
    if (tid < 128) {
        sh_bias[tid] = bias[tid];
        if (MODE == 1) {
            float mu = g_stats[tid] * inv_n;
            float var = fmaf(-mu, mu, g_stats[128 + tid] * inv_n);
            float rs = rsqrtf(var + BN_EPS);
            float sc = gamma[tid] * rs;
            sh_scale[tid] = sc;
            sh_shift[tid] = fmaf(-mu, sc, beta[tid]);
        }
    }
    {
        uint4* dw = (uint4*)(smem + SM_BW);
        for (int i = tid; i < PLANE_BYTES / 16; i += 256)
            dw[i] = __ldg(&Wimg[i]);
    }
    if (MODE == 1) __syncthreads();

    for (int tile = blockIdx.x; tile < ntiles; tile += gridDim.x) {
        int block_row = tile * 128;

        // ---- A tile ----
        if (MODE == 0) {
            int r = tid >> 1, half = tid & 1;
            int grow = block_row + r;
            uint32_t dbase = (uint32_t)r * (APITCH * 2) + half * 128;
            const uint4* srch = Ahi + (size_t)grow * 16 + half * 8;
#pragma unroll
            for (int i = 0; i < 8; i++) {
                uint4 vh = (grow < nrows) ? __ldg(&srch[i]) : make_uint4(0, 0, 0, 0);
                *reinterpret_cast<uint4*>(smem + SM_AHI + dbase + i * 16) = vh;
            }
        } else {
            int r = tid >> 1, half = tid & 1;
            int grow = block_row + r;
            // fp16 z row: 64 halves per thread = 8 x uint4(8 halves)
            const uint4* arow = Azh + ((size_t)grow * HH + half * 64) / 8;
            uint32_t dbase = (uint32_t)r * (APITCH * 2) + half * 128;
#pragma unroll
            for (int i = 0; i < 8; i++) {
                uint4 vz = (grow < nrows) ? __ldg(&arow[i]) : make_uint4(0, 0, 0, 0);
                uint32_t zin[4] = {vz.x, vz.y, vz.z, vz.w};
                uint32_t zo[4];
                int c0 = half * 64 + i * 8;
#pragma unroll
                for (int j = 0; j < 4; j++) {
                    float2 f = __half22float2(*reinterpret_cast<__half2*>(&zin[j]));
                    float t0 = fmaxf(fmaf(f.x, sh_scale[c0 + 2 * j], sh_shift[c0 + 2 * j]), 0.f);
                    float t1 = fmaxf(fmaf(f.y, sh_scale[c0 + 2 * j + 1], sh_shift[c0 + 2 * j + 1]), 0.f);
                    __half2 hp = __floats2half2_rn(t0, t1);
                    zo[j] = *reinterpret_cast<uint32_t*>(&hp);
                }
                *reinterpret_cast<uint4*>(smem + SM_AHI + dbase + i * 16) =
                    make_uint4(zo[0], zo[1], zo[2], zo[3]);
            }
        }
        __syncthreads();

        // ---- mainloop: 8 k-steps of 16; single term ----
        float acc[4][4][4] = {};
#pragma unroll
        for (int ks = 0; ks < 8; ks++) {
            uint32_t kb = (uint32_t)ks * 32 + tig * 4;
            uint32_t ah[4][4], bw[4][2];
#pragma unroll
            for (int mf = 0; mf < 4; mf++) {
                uint32_t base = (uint32_t)(warp_m * 64 + mf * 16 + groupID) * (APITCH * 2) + kb;
                ah[mf][0] = *(const uint32_t*)(smem + SM_AHI + base);
                ah[mf][1] = *(const uint32_t*)(smem + SM_AHI + base + 8 * APITCH * 2);
                ah[mf][2] = *(const uint32_t*)(smem + SM_AHI + base + 16);
                ah[mf][3] = *(const uint32_t*)(smem + SM_AHI + base + 8 * APITCH * 2 + 16);
            }
#pragma unroll
            for (int nf = 0; nf < 4; nf++) {
                uint32_t base = (uint32_t)(warp_n * 32 + nf * 8 + groupID) * (APITCH * 2) + kb;
                bw[nf][0] = *(const uint32_t*)(smem + SM_BW + base);
                bw[nf][1] = *(const uint32_t*)(smem + SM_BW + base + 16);
            }
#pragma unroll
            for (int mf = 0; mf < 4; mf++)
#pragma unroll
                for (int nf = 0; nf < 4; nf++)
                    mma16816(acc[mf][nf], ah[mf], bw[nf]);
        }

        // ---- epilogue: bias (+relu MODE1), fp16 store; stats (MODE 0) ----
        float cs[4][2] = {}, cq[4][2] = {};
#pragma unroll
        for (int mf = 0; mf < 4; mf++) {
            int r0 = block_row + warp_m * 64 + mf * 16 + groupID;
            int r1 = r0 + 8;
#pragma unroll
            for (int nf = 0; nf < 4; nf++) {
                int c0 = warp_n * 32 + nf * 8 + 2 * tig;
                float b0 = sh_bias[c0], b1 = sh_bias[c0 + 1];
                float t00 = acc[mf][nf][0] + b0, t01 = acc[mf][nf][1] + b1;
                float t10 = acc[mf][nf][2] + b0, t11 = acc[mf][nf][3] + b1;
                if (MODE == 1) {
                    t00 = fmaxf(t00, 0.f); t01 = fmaxf(t01, 0.f);
                    t10 = fmaxf(t10, 0.f); t11 = fmaxf(t11, 0.f);
                }
                if (r0 < nrows) {
                    *reinterpret_cast<__half2*>(out + (size_t)r0 * HH + c0) =
                        __floats2half2_rn(t00, t01);
                    if (MODE == 0) {
                        cs[nf][0] += t00; cq[nf][0] = fmaf(t00, t00, cq[nf][0]);
                        cs[nf][1] += t01; cq[nf][1] = fmaf(t01, t01, cq[nf][1]);
                    }
                }
                if (r1 < nrows) {
                    *reinterpret_cast<__half2*>(out + (size_t)r1 * HH + c0) =
                        __floats2half2_rn(t10, t11);
                    if (MODE == 0) {
                        cs[nf][0] += t10; cq[nf][0] = fmaf(t10, t10, cq[nf][0]);
                        cs[nf][1] += t11; cq[nf][1] = fmaf(t11, t11, cq[nf][1]);
                    }
                }
            }
        }
        if (MODE == 0) {
#pragma unroll
            for (int nf = 0; nf < 4; nf++)
#pragma unroll
                for (int j = 0; j < 2; j++) {
                    float s = cs[nf][j], q = cq[nf][j];
#pragma unroll
                    for (int off = 16; off >= 4; off >>= 1) {
                        s += __shfl_down_sync(0xffffffff, s, off);
                        q += __shfl_down_sync(0xffffffff, q, off);
                    }
                    if (lane < 4) {
                        int col = warp_n * 32 + nf * 8 + 2 * lane + j;
                        atomicAdd(&g_stats[col], s);
                        atomicAdd(&g_stats[128 + col], q);
                    }
                }
        }
        __syncthreads();   // A smem reusable next tile
    }
}

// ---------------- segment-CSR readout (fp16 h) ----------------
__global__ void readout_kernel(const __half* __restrict__ h,
                               const int* __restrict__ ptr,
                               float* __restrict__ out) {
    int g = blockIdx.x;
    int c = threadIdx.x;
    int s = ptr[g], e = ptr[g + 1];
    float acc = 0.f;
    for (int r = s; r < e; r++) acc += __half2float(h[(size_t)r * HH + c]);
    out[g * HH + c] = acc;
}

// ---------------- host launch ----------------
extern "C" void kernel_launch(void* const* d_in, const int* in_sizes, int n_in,
                              void* d_out, int out_size) {
    const float* x = (const float*)d_in[0];
    const int* src = (const int*)d_in[1];
    const int* dst = (const int*)d_in[2];
    const int* ptr = (const int*)d_in[3];
    int E = in_sizes[1];
    int N = in_sizes[0] / HH;
    int G = in_sizes[3] - 1;
    float* out = (float*)d_out;

    unsigned short *z, *hA, *hB;
    int *deg, *slot, *rowstart, *csr;
    uint2* ahi;
    unsigned short* wimg;
    cudaGetSymbolAddress((void**)&z, g_z);
    cudaGetSymbolAddress((void**)&hA, g_hA);
    cudaGetSymbolAddress((void**)&hB, g_hB);
    cudaGetSymbolAddress((void**)&deg, g_deg);
    cudaGetSymbolAddress((void**)&slot, g_slot);
    cudaGetSymbolAddress((void**)&rowstart, g_rowstart);
    cudaGetSymbolAddress((void**)&csr, g_csr);
    cudaGetSymbolAddress((void**)&ahi, g_ahi);
    cudaGetSymbolAddress((void**)&wimg, g_w);

    cudaFuncSetAttribute(gemm_mma<0>, cudaFuncAttributeMaxDynamicSharedMemorySize, SM_TOTAL);
    cudaFuncSetAttribute(gemm_mma<1>, cudaFuncAttributeMaxDynamicSharedMemorySize, SM_TOTAL);

    int ntiles = (N + 127) / 128;
    int gemm_grid = ntiles < 148 ? ntiles : 148;
    int eb = (E + 255) / 256;
    int agg_blocks = (int)(((long long)N * 32 + 255) / 256);
    float inv_n = 1.0f / (float)N;

    int zero_blocks = (N + 255) / 256;
    prep_kernel<<<384 + zero_blocks, 256>>>(
        (const float*)d_in[4], (const float*)d_in[8],
        (const float*)d_in[10], (const float*)d_in[14],
        (const float*)d_in[16], (const float*)d_in[20], N);
    count_kernel<<<eb, 256>>>(dst, deg, slot, E);
    scan_kernel<<<1, 1024>>>(deg, rowstart, N);
    fill_kernel<<<eb, 256>>>(src, dst, rowstart, slot, csr, E);

    auto layer = [&](const void* hin, bool hin_f16, unsigned short* hout, int li) {
        int base = 4 + 6 * li;
        const float* ba = (const float*)d_in[base + 1];
        const float* ga = (const float*)d_in[base + 2];
        const float* be = (const float*)d_in[base + 3];
        const float* bb = (const float*)d_in[base + 5];
        const uint4* wa_img = (const uint4*)(wimg + (size_t)(2 * li + 0) * WIMG_ELEMS);
        const uint4* wb_img = (const uint4*)(wimg + (size_t)(2 * li + 1) * WIMG_ELEMS);

        if (hin_f16)
            aggregate_f16_kernel<<<agg_blocks, 256>>>((const uint2*)hin, rowstart,
                                                      csr, ahi, N);
        else
            aggregate_f32_kernel<<<agg_blocks, 256>>>((const float4*)hin, rowstart,
                                                      csr, ahi, N);
        gemm_mma<0><<<gemm_grid, 256, SM_TOTAL>>>(
            nullptr, (const uint4*)ahi, wa_img,
            ba, nullptr, nullptr, 0.f, (__half*)z, N, ntiles);
        gemm_mma<1><<<gemm_grid, 256, SM_TOTAL>>>(
            (const uint4*)z, nullptr, wb_img,
            bb, ga, be, inv_n, (__half*)hout, N, ntiles);
    };

    layer(x, false, hA, 0);
    layer(hA, true, hB, 1);
    layer(hB, true, hA, 2);

    readout_kernel<<<G, 128>>>((const __half*)hA, ptr, out);
}